// round 2
// baseline (speedup 1.0000x reference)
#include <cuda_runtime.h>
#include <cuda_bf16.h>
#include <math.h>

// Problem constants
#define B_  4096
#define T_  200
#define E_  64
#define A1_ 64
#define A2_ 32
#define M1_ 256
#define M2_ 128

// -------- device scratch (no allocations allowed) --------
__device__ float g_Wh[64 * 64];     // aw1[0:64] + aw1[128:192]
__device__ float g_Wq[64 * 64];     // aw1[64:128] - aw1[128:192]
__device__ float g_Wp[64 * 64];     // aw1[192:256]
__device__ float g_qb[B_ * 64];     // per-batch layer1 bias: ab1 + item @ Wq
__device__ float g_item[B_ * 64];   // gathered item embeddings
__device__ float g_inter[B_ * 64];  // interest vectors

// ============================================================
// prep 1: fold aw1 into Wh / Wq / Wp
// ============================================================
__global__ void prep_weights(const float* __restrict__ aw1) {
    int idx = blockIdx.x * blockDim.x + threadIdx.x;
    if (idx >= 64 * 64) return;
    int j = idx & 63, k = idx >> 6;
    float a = aw1[k * 64 + j];
    float b = aw1[(64 + k) * 64 + j];
    float c = aw1[(128 + k) * 64 + j];
    float d = aw1[(192 + k) * 64 + j];
    g_Wh[k * 64 + j] = a + c;
    g_Wq[k * 64 + j] = b - c;
    g_Wp[k * 64 + j] = d;
}

// ============================================================
// prep 2: gather item embedding, compute per-batch qb = ab1 + item @ Wq
// grid: B_ blocks of 64 threads
// ============================================================
__global__ void prep_batch(const int* __restrict__ target,
                           const float* __restrict__ table,
                           const float* __restrict__ ab1) {
    __shared__ float it[64];
    int b = blockIdx.x;
    int j = threadIdx.x;
    it[j] = table[(size_t)target[b] * 64 + j];
    __syncthreads();
    float acc = ab1[j];
#pragma unroll
    for (int k = 0; k < 64; ++k)
        acc = fmaf(it[k], g_Wq[k * 64 + j], acc);
    g_qb[b * 64 + j] = acc;
    g_item[b * 64 + j] = it[j];
}

// ============================================================
// main kernel: one CTA per batch element.
//   smem: hist tile [200,64], folded Wc (col-major, pitch 68),
//         aw2 (col-major pitch 68), per-warp h1 staging, softmax scratch.
//   8 warps; each warp owns 25 tokens, processed in 5 tiles of 5 tokens.
// ============================================================

// smem layout (float offsets); all float4-aligned where needed
#define OFF_HIST  0                    // 200*64 = 12800
#define OFF_WC    12800                // 64*68  = 4352
#define OFF_AW2   17152                // 32*68  = 2176
#define OFF_H1    19328                // 8*5*64 = 2560
#define OFF_QB    21888                // 64
#define OFF_AB2   21952                // 32
#define OFF_AOW   21984                // 32
#define OFF_SC    22016                // 208 (200 used)
#define OFF_RED   22224                // 256 interest partials
#define OFF_WRED  22480                // 32 reduce scratch
#define OFF_QV    22512                // 64
#define SMEM_B_FLOATS 22576
#define SMEM_B_BYTES  (SMEM_B_FLOATS * 4)

__global__ __launch_bounds__(256) void din_main(
    const int* __restrict__ hist_id,
    const int* __restrict__ mask,        // bool promoted to 4-byte; test != 0
    const float* __restrict__ table,
    const float* __restrict__ aw2,
    const float* __restrict__ ab2,
    const float* __restrict__ aow,
    const float* __restrict__ aob) {
    extern __shared__ float sm[];
    const int b   = blockIdx.x;
    const int tid = threadIdx.x;
    const int w   = tid >> 5;
    const int l   = tid & 31;

    // --- stage small vectors ---
    if (tid < 64)                      sm[OFF_QV + tid]        = g_item[b * 64 + tid];
    else if (tid < 128)                sm[OFF_QB + tid - 64]   = g_qb[b * 64 + tid - 64];
    else if (tid < 160)                sm[OFF_AB2 + tid - 128] = ab2[tid - 128];
    else if (tid < 192)                sm[OFF_AOW + tid - 160] = aow[tid - 160];
    __syncthreads();   // qv needed below

    // --- fold Wc[k][j] = Wh[k][j] + q[k]*Wp[k][j]; store column-major pitch 68 ---
    for (int idx = tid; idx < 64 * 64; idx += 256) {
        int j = idx & 63, k = idx >> 6;
        sm[OFF_WC + j * 68 + k] = fmaf(sm[OFF_QV + k], g_Wp[k * 64 + j], g_Wh[k * 64 + j]);
    }
    // aw2 column-major pitch 68
    for (int idx = tid; idx < 64 * 32; idx += 256) {
        int j = idx & 31, k = idx >> 5;
        sm[OFF_AW2 + j * 68 + k] = aw2[k * 32 + j];
    }
    // gather history embeddings (float4, 16 threads per row)
    {
        const float4* tab4 = (const float4*)table;
        float4* hist4 = (float4*)(sm + OFF_HIST);
        for (int idx = tid; idx < T_ * 16; idx += 256) {
            int t = idx >> 4, v = idx & 15;
            hist4[t * 16 + v] = tab4[(size_t)hist_id[b * T_ + t] * 16 + v];
        }
    }
    __syncthreads();

    const float4* wc4  = (const float4*)(sm + OFF_WC);
    const float4* h4   = (const float4*)(sm + OFF_HIST);
    const float4* a24  = (const float4*)(sm + OFF_AW2);
    const float4* h1s4 = (const float4*)(sm + OFF_H1);
    const float aob0 = aob[0];

    const int t0 = w * 25;      // 25 tokens per warp
    const float qbA = sm[OFF_QB + l];
    const float qbB = sm[OFF_QB + 32 + l];
    const float b2  = sm[OFF_AB2 + l];
    const float awl = sm[OFF_AOW + l];

    for (int tile = 0; tile < 5; ++tile) {
        const int tt0 = t0 + tile * 5;
        // ---- layer 1: h1[t][j] for j=l, l+32 ----
        float accA[5], accB[5];
#pragma unroll
        for (int t = 0; t < 5; ++t) { accA[t] = qbA; accB[t] = qbB; }
#pragma unroll
        for (int kq = 0; kq < 16; ++kq) {
            float4 wA = wc4[l * 17 + kq];
            float4 wB = wc4[(l + 32) * 17 + kq];
#pragma unroll
            for (int t = 0; t < 5; ++t) {
                float4 x = h4[(tt0 + t) * 16 + kq];
                accA[t] = fmaf(x.x, wA.x, fmaf(x.y, wA.y, fmaf(x.z, wA.z, fmaf(x.w, wA.w, accA[t]))));
                accB[t] = fmaf(x.x, wB.x, fmaf(x.y, wB.y, fmaf(x.z, wB.z, fmaf(x.w, wB.w, accB[t]))));
            }
        }
#pragma unroll
        for (int t = 0; t < 5; ++t) {
            sm[OFF_H1 + (w * 5 + t) * 64 + l]      = fmaxf(accA[t], 0.f);
            sm[OFF_H1 + (w * 5 + t) * 64 + 32 + l] = fmaxf(accB[t], 0.f);
        }
        __syncwarp();
        // ---- layer 2: h2[t][l] (A2=32 outputs, one per lane) ----
        float acc2[5];
#pragma unroll
        for (int t = 0; t < 5; ++t) acc2[t] = b2;
#pragma unroll
        for (int kq = 0; kq < 16; ++kq) {
            float4 wv = a24[l * 17 + kq];
#pragma unroll
            for (int t = 0; t < 5; ++t) {
                float4 hv = h1s4[(w * 5 + t) * 16 + kq];
                acc2[t] = fmaf(hv.x, wv.x, fmaf(hv.y, wv.y, fmaf(hv.z, wv.z, fmaf(hv.w, wv.w, acc2[t]))));
            }
        }
        // ---- layer 3: score via warp reduce ----
#pragma unroll
        for (int t = 0; t < 5; ++t) {
            float p = fmaxf(acc2[t], 0.f) * awl;
            p += __shfl_xor_sync(0xffffffffu, p, 16);
            p += __shfl_xor_sync(0xffffffffu, p, 8);
            p += __shfl_xor_sync(0xffffffffu, p, 4);
            p += __shfl_xor_sync(0xffffffffu, p, 2);
            p += __shfl_xor_sync(0xffffffffu, p, 1);
            if (l == 0) {
                int tt = tt0 + t;
                float s = p + aob0;
                sm[OFF_SC + tt] = (mask[b * T_ + tt] != 0) ? s : -1e9f;
            }
        }
        __syncwarp();
    }
    __syncthreads();

    // ---- softmax over 200 scores ----
    float v = (tid < T_) ? sm[OFF_SC + tid] : -1e30f;
    float m = v;
    m = fmaxf(m, __shfl_xor_sync(0xffffffffu, m, 16));
    m = fmaxf(m, __shfl_xor_sync(0xffffffffu, m, 8));
    m = fmaxf(m, __shfl_xor_sync(0xffffffffu, m, 4));
    m = fmaxf(m, __shfl_xor_sync(0xffffffffu, m, 2));
    m = fmaxf(m, __shfl_xor_sync(0xffffffffu, m, 1));
    if (l == 0) sm[OFF_WRED + w] = m;
    __syncthreads();
    if (tid == 0) {
        float mm = sm[OFF_WRED];
#pragma unroll
        for (int i = 1; i < 8; ++i) mm = fmaxf(mm, sm[OFF_WRED + i]);
        sm[OFF_WRED + 16] = mm;
    }
    __syncthreads();
    m = sm[OFF_WRED + 16];
    float e = (tid < T_) ? __expf(v - m) : 0.f;
    float s = e;
    s += __shfl_xor_sync(0xffffffffu, s, 16);
    s += __shfl_xor_sync(0xffffffffu, s, 8);
    s += __shfl_xor_sync(0xffffffffu, s, 4);
    s += __shfl_xor_sync(0xffffffffu, s, 2);
    s += __shfl_xor_sync(0xffffffffu, s, 1);
    if (l == 0) sm[OFF_WRED + 8 + w] = s;
    __syncthreads();
    if (tid == 0) {
        float ss = 0.f;
#pragma unroll
        for (int i = 0; i < 8; ++i) ss += sm[OFF_WRED + 8 + i];
        sm[OFF_WRED + 17] = 1.f / ss;
    }
    __syncthreads();
    float inv = sm[OFF_WRED + 17];
    if (tid < T_) sm[OFF_SC + tid] = e * inv;
    __syncthreads();

    // ---- interest = sum_t w[t] * hist[t][:] ----
    {
        int j = tid & 63, g = tid >> 6;  // 4 groups of 50 tokens
        float acc = 0.f;
        for (int t = g * 50; t < (g + 1) * 50; ++t)
            acc = fmaf(sm[OFF_SC + t], sm[OFF_HIST + t * 64 + j], acc);
        sm[OFF_RED + g * 64 + j] = acc;
    }
    __syncthreads();
    if (tid < 64) {
        float iv = sm[OFF_RED + tid] + sm[OFF_RED + 64 + tid] +
                   sm[OFF_RED + 128 + tid] + sm[OFF_RED + 192 + tid];
        g_inter[b * 64 + tid] = iv;
    }
}

// ============================================================
// final MLP: [B,128] -> 256 -> 128 -> 1
// grid 256 CTAs x 256 threads, 16 batch rows per CTA.
// ============================================================
#define C_XS   0        // 16*128 = 2048
#define C_WT   2048     // 8192 (reused: 32x256 then 32x128 tiles)
#define C_G1   10240    // 16*256 = 4096
#define C_MB1  14336    // 256
#define C_MB2  14592    // 128
#define C_OW   14720    // 128
#define SMEM_C_FLOATS 14848
#define SMEM_C_BYTES  (SMEM_C_FLOATS * 4)

__global__ __launch_bounds__(256) void din_final(
    const float* __restrict__ mw1, const float* __restrict__ mb1,
    const float* __restrict__ mw2, const float* __restrict__ mb2,
    const float* __restrict__ ow,  const float* __restrict__ ob,
    float* __restrict__ out) {
    extern __shared__ float sm[];
    const int tid = threadIdx.x;
    const int b0  = blockIdx.x * 16;
    const int r   = tid >> 4;   // 0..15 row within tile
    const int jg  = tid & 15;   // column group

    // X = concat(item, interest)
    for (int idx = tid; idx < 16 * 128; idx += 256) {
        int rr = idx >> 7, c = idx & 127;
        sm[C_XS + idx] = (c < 64) ? g_item[(b0 + rr) * 64 + c]
                                  : g_inter[(b0 + rr) * 64 + (c - 64)];
    }
    sm[C_MB1 + tid] = mb1[tid];
    if (tid < 128) { sm[C_MB2 + tid] = mb2[tid]; sm[C_OW + tid] = ow[tid]; }
    __syncthreads();

    // ---- stage 1: g1 = relu(X @ mw1 + mb1) ; thread covers j = jg*4 + jj*64 + c ----
    float a1[16];
#pragma unroll
    for (int jj = 0; jj < 4; ++jj)
#pragma unroll
        for (int c = 0; c < 4; ++c)
            a1[jj * 4 + c] = sm[C_MB1 + jg * 4 + jj * 64 + c];

    for (int kt = 0; kt < 4; ++kt) {
        for (int idx = tid; idx < 32 * 256; idx += 256) {
            int row = idx >> 8, col = idx & 255;
            sm[C_WT + idx] = mw1[(kt * 32 + row) * 256 + col];
        }
        __syncthreads();
        const float4* wbase = (const float4*)(sm + C_WT);
#pragma unroll
        for (int k = 0; k < 32; ++k) {
            float xk = sm[C_XS + r * 128 + kt * 32 + k];
            float4 w0 = wbase[k * 64 + jg];
            float4 w1 = wbase[k * 64 + 16 + jg];
            float4 w2 = wbase[k * 64 + 32 + jg];
            float4 w3 = wbase[k * 64 + 48 + jg];
            a1[0]  = fmaf(xk, w0.x, a1[0]);  a1[1]  = fmaf(xk, w0.y, a1[1]);
            a1[2]  = fmaf(xk, w0.z, a1[2]);  a1[3]  = fmaf(xk, w0.w, a1[3]);
            a1[4]  = fmaf(xk, w1.x, a1[4]);  a1[5]  = fmaf(xk, w1.y, a1[5]);
            a1[6]  = fmaf(xk, w1.z, a1[6]);  a1[7]  = fmaf(xk, w1.w, a1[7]);
            a1[8]  = fmaf(xk, w2.x, a1[8]);  a1[9]  = fmaf(xk, w2.y, a1[9]);
            a1[10] = fmaf(xk, w2.z, a1[10]); a1[11] = fmaf(xk, w2.w, a1[11]);
            a1[12] = fmaf(xk, w3.x, a1[12]); a1[13] = fmaf(xk, w3.y, a1[13]);
            a1[14] = fmaf(xk, w3.z, a1[14]); a1[15] = fmaf(xk, w3.w, a1[15]);
        }
        __syncthreads();
    }
#pragma unroll
    for (int jj = 0; jj < 4; ++jj)
#pragma unroll
        for (int c = 0; c < 4; ++c)
            sm[C_G1 + r * 256 + jg * 4 + jj * 64 + c] = fmaxf(a1[jj * 4 + c], 0.f);
    __syncthreads();

    // ---- stage 2: g2 = relu(g1 @ mw2 + mb2); thread covers j = jg*4 + jj*64 + c, jj<2 ----
    float a2[8];
#pragma unroll
    for (int jj = 0; jj < 2; ++jj)
#pragma unroll
        for (int c = 0; c < 4; ++c)
            a2[jj * 4 + c] = sm[C_MB2 + jg * 4 + jj * 64 + c];

    for (int kt = 0; kt < 8; ++kt) {
        for (int idx = tid; idx < 32 * 128; idx += 256) {
            int row = idx >> 7, col = idx & 127;
            sm[C_WT + idx] = mw2[(kt * 32 + row) * 128 + col];
        }
        __syncthreads();
        const float4* wbase = (const float4*)(sm + C_WT);
#pragma unroll
        for (int k = 0; k < 32; ++k) {
            float gk = sm[C_G1 + r * 256 + kt * 32 + k];
            float4 w0 = wbase[k * 32 + jg];
            float4 w1 = wbase[k * 32 + 16 + jg];
            a2[0] = fmaf(gk, w0.x, a2[0]); a2[1] = fmaf(gk, w0.y, a2[1]);
            a2[2] = fmaf(gk, w0.z, a2[2]); a2[3] = fmaf(gk, w0.w, a2[3]);
            a2[4] = fmaf(gk, w1.x, a2[4]); a2[5] = fmaf(gk, w1.y, a2[5]);
            a2[6] = fmaf(gk, w1.z, a2[6]); a2[7] = fmaf(gk, w1.w, a2[7]);
        }
        __syncthreads();
    }

    // ---- stage 3: out = g2 @ ow + ob, reduce across 16-thread row groups ----
    float p = 0.f;
#pragma unroll
    for (int jj = 0; jj < 2; ++jj)
#pragma unroll
        for (int c = 0; c < 4; ++c) {
            int j = jg * 4 + jj * 64 + c;
            p = fmaf(fmaxf(a2[jj * 4 + c], 0.f), sm[C_OW + j], p);
        }
    p += __shfl_xor_sync(0xffffffffu, p, 8);
    p += __shfl_xor_sync(0xffffffffu, p, 4);
    p += __shfl_xor_sync(0xffffffffu, p, 2);
    p += __shfl_xor_sync(0xffffffffu, p, 1);
    if (jg == 0) out[b0 + r] = p + ob[0];
}

// ============================================================
// launch
// ============================================================
extern "C" void kernel_launch(void* const* d_in, const int* in_sizes, int n_in,
                              void* d_out, int out_size) {
    const int*   target  = (const int*)d_in[0];
    const int*   hist_id = (const int*)d_in[1];
    const int*   mask    = (const int*)d_in[2];     // bool promoted; test != 0
    const float* table   = (const float*)d_in[3];
    const float* aw1     = (const float*)d_in[4];
    const float* ab1     = (const float*)d_in[5];
    const float* aw2     = (const float*)d_in[6];
    const float* ab2     = (const float*)d_in[7];
    const float* aow     = (const float*)d_in[8];
    const float* aob     = (const float*)d_in[9];
    const float* mw1     = (const float*)d_in[10];
    const float* mb1     = (const float*)d_in[11];
    const float* mw2     = (const float*)d_in[12];
    const float* mb2     = (const float*)d_in[13];
    const float* ow      = (const float*)d_in[14];
    const float* ob      = (const float*)d_in[15];
    float* out = (float*)d_out;

    cudaFuncSetAttribute(din_main, cudaFuncAttributeMaxDynamicSharedMemorySize, SMEM_B_BYTES);
    cudaFuncSetAttribute(din_final, cudaFuncAttributeMaxDynamicSharedMemorySize, SMEM_C_BYTES);

    prep_weights<<<8, 512>>>(aw1);
    prep_batch<<<B_, 64>>>(target, table, ab1);
    din_main<<<B_, 256, SMEM_B_BYTES>>>(hist_id, mask, table, aw2, ab2, aow, aob);
    din_final<<<B_ / 16, 256, SMEM_C_BYTES>>>(mw1, mb1, mw2, mb2, ow, ob, out);
}

// round 3
// speedup vs baseline: 1.4615x; 1.4615x over previous
#include <cuda_runtime.h>
#include <cuda_bf16.h>
#include <math.h>

// Problem constants
#define B_  4096
#define T_  200
#define E_  64
#define A1_ 64
#define A2_ 32
#define M1_ 256
#define M2_ 128

// -------- device scratch (no allocations allowed) --------
__device__ float g_Wh[64 * 64];     // aw1[0:64] + aw1[128:192]
__device__ float g_Wq[64 * 64];     // aw1[64:128] - aw1[128:192]
__device__ float g_Wp[64 * 64];     // aw1[192:256]
__device__ float g_qb[B_ * 64];     // per-batch layer1 bias: ab1 + item @ Wq
__device__ float g_item[B_ * 64];   // gathered item embeddings
__device__ float g_inter[B_ * 64];  // interest vectors

// ---- tf32 helpers ----
__device__ __forceinline__ unsigned int f2tf(float f) {
    unsigned int r;
    asm("cvt.rna.tf32.f32 %0, %1;" : "=r"(r) : "f"(f));
    return r;
}
__device__ __forceinline__ void mma_tf32(
    float& c0, float& c1, float& c2, float& c3,
    unsigned int a0, unsigned int a1, unsigned int a2, unsigned int a3,
    unsigned int b0, unsigned int b1) {
    asm("mma.sync.aligned.m16n8k8.row.col.f32.tf32.tf32.f32 "
        "{%0,%1,%2,%3},{%4,%5,%6,%7},{%8,%9},{%0,%1,%2,%3};"
        : "+f"(c0), "+f"(c1), "+f"(c2), "+f"(c3)
        : "r"(a0), "r"(a1), "r"(a2), "r"(a3), "r"(b0), "r"(b1));
}

// ============================================================
// prep 1: fold aw1 into Wh / Wq / Wp
// ============================================================
__global__ void prep_weights(const float* __restrict__ aw1) {
    int idx = blockIdx.x * blockDim.x + threadIdx.x;
    if (idx >= 64 * 64) return;
    int j = idx & 63, k = idx >> 6;
    float a = aw1[k * 64 + j];
    float b = aw1[(64 + k) * 64 + j];
    float c = aw1[(128 + k) * 64 + j];
    float d = aw1[(192 + k) * 64 + j];
    g_Wh[k * 64 + j] = a + c;
    g_Wq[k * 64 + j] = b - c;
    g_Wp[k * 64 + j] = d;
}

// ============================================================
// prep 2: gather item embedding, compute per-batch qb = ab1 + item @ Wq
// ============================================================
__global__ void prep_batch(const int* __restrict__ target,
                           const float* __restrict__ table,
                           const float* __restrict__ ab1) {
    __shared__ float it[64];
    int b = blockIdx.x;
    int j = threadIdx.x;
    it[j] = table[(size_t)target[b] * 64 + j];
    __syncthreads();
    float acc = ab1[j];
#pragma unroll
    for (int k = 0; k < 64; ++k)
        acc = fmaf(it[k], g_Wq[k * 64 + j], acc);
    g_qb[b * 64 + j] = acc;
    g_item[b * 64 + j] = it[j];
}

// ============================================================
// main kernel: one CTA (512 threads) per batch element, tf32 tensor cores
// for attention layers 1 & 2; fp32 softmax + interest.
// ============================================================
#define PH 68    // smem pitch (floats): 68 mod 32 = 4, so 8 rows x 4 = 32 banks
// smem layout (float offsets)
#define OFF_HIST  0        // 208*68 = 14144
#define OFF_H1    14144    // 208*68 = 14144 -> 28288
#define OFF_WC    28288    // 64*68  = 4352  -> 32640 (folded layer1 W, [k][n])
#define OFF_W2    32640    // 64*36  = 2304  -> 34944 (aw2, [k][n], pitch 36)
#define OFF_QV    34944    // 64
#define OFF_QB    35008    // 64
#define OFF_AB2   35072    // 32
#define OFF_AOW   35104    // 32
#define OFF_SCP   35136    // 4*208 = 832 -> 35968 (score partials per n-tile)
#define OFF_SC    35968    // 208 -> 36176
#define OFF_WRED  36176    // 48  -> 36224 ([0:16] max, [16] gmax, [17:33] sums, [33] inv)
#define OFF_RED   36224    // 512 -> 36736
#define SMEM_B_FLOATS 36736
#define SMEM_B_BYTES  (SMEM_B_FLOATS * 4)

__global__ __launch_bounds__(512) void din_main(
    const int* __restrict__ hist_id,
    const int* __restrict__ mask,        // bool promoted to 4-byte; test != 0
    const float* __restrict__ table,
    const float* __restrict__ aw2,
    const float* __restrict__ ab2,
    const float* __restrict__ aow,
    const float* __restrict__ aob) {
    extern __shared__ float sm[];
    const int b   = blockIdx.x;
    const int tid = threadIdx.x;
    const int w   = tid >> 5;
    const int l   = tid & 31;
    const int l4  = l >> 2;   // 0..7
    const int lm  = l & 3;    // 0..3

    // --- stage small vectors ---
    if (tid < 64)        sm[OFF_QV + tid]        = g_item[b * 64 + tid];
    else if (tid < 128)  sm[OFF_QB + tid - 64]   = g_qb[b * 64 + tid - 64];
    else if (tid < 160)  sm[OFF_AB2 + tid - 128] = ab2[tid - 128];
    else if (tid < 192)  sm[OFF_AOW + tid - 160] = aow[tid - 160];
    __syncthreads();   // qv needed for Wc fold

    // --- fold Wc[k][n] = Wh[k][n] + q[k]*Wp[k][n] (row-major by k, pitch 68) ---
    for (int idx = tid; idx < 64 * 64; idx += 512) {
        int n = idx & 63, k = idx >> 6;
        sm[OFF_WC + k * PH + n] = fmaf(sm[OFF_QV + k], g_Wp[k * 64 + n], g_Wh[k * 64 + n]);
    }
    // --- stage aw2 [k][n] pitch 36 ---
    for (int idx = tid; idx < 64 * 32; idx += 512) {
        int n = idx & 31, k = idx >> 5;
        sm[OFF_W2 + k * 36 + n] = aw2[k * 32 + n];
    }
    // --- gather history embeddings (float4; row stride 68 floats = 17 float4) ---
    {
        const float4* tab4 = (const float4*)table;
        float4* hist4 = (float4*)(sm + OFF_HIST);
        for (int idx = tid; idx < T_ * 16; idx += 512) {
            int t = idx >> 4, v = idx & 15;
            hist4[t * 17 + v] = tab4[(size_t)hist_id[b * T_ + t] * 16 + v];
        }
        // zero-pad rows 200..207 (keeps mma inputs finite)
        for (int idx = tid; idx < 8 * 17; idx += 512) {
            int t = 200 + idx / 17, v = idx % 17;
            hist4[t * 17 + v] = make_float4(0.f, 0.f, 0.f, 0.f);
        }
    }
    __syncthreads();

    // ================= layer 1 (tf32 mma): H1[208,64] = HIST @ Wc + qb, relu =====
    {
        const int nt = w & 7;           // n-tile (8 cols)
        const int ncol = nt * 8 + l4;
        unsigned int B0[8], B1[8];
#pragma unroll
        for (int kk = 0; kk < 8; ++kk) {
            B0[kk] = f2tf(sm[OFF_WC + (kk * 8 + lm) * PH + ncol]);
            B1[kk] = f2tf(sm[OFF_WC + (kk * 8 + lm + 4) * PH + ncol]);
        }
        const float bc0 = sm[OFF_QB + nt * 8 + 2 * lm];
        const float bc1 = sm[OFF_QB + nt * 8 + 2 * lm + 1];
        const int mt_beg = (w >> 3) ? 7 : 0;
        const int mt_end = (w >> 3) ? 13 : 7;
        for (int mt = mt_beg; mt < mt_end; ++mt) {
            float c0 = bc0, c1 = bc1, c2 = bc0, c3 = bc1;
            const int arow = mt * 16 + l4;
            const float* ab = sm + OFF_HIST + arow * PH + lm;
#pragma unroll
            for (int kk = 0; kk < 8; ++kk) {
                unsigned int a0 = f2tf(ab[kk * 8]);
                unsigned int a1 = f2tf(ab[8 * PH + kk * 8]);
                unsigned int a2 = f2tf(ab[kk * 8 + 4]);
                unsigned int a3 = f2tf(ab[8 * PH + kk * 8 + 4]);
                mma_tf32(c0, c1, c2, c3, a0, a1, a2, a3, B0[kk], B1[kk]);
            }
            float2 lo = make_float2(fmaxf(c0, 0.f), fmaxf(c1, 0.f));
            float2 hi = make_float2(fmaxf(c2, 0.f), fmaxf(c3, 0.f));
            *(float2*)(sm + OFF_H1 + arow * PH + nt * 8 + 2 * lm)       = lo;
            *(float2*)(sm + OFF_H1 + (arow + 8) * PH + nt * 8 + 2 * lm) = hi;
        }
    }
    __syncthreads();

    // ======= layer 2 (tf32 mma) + score: C2[208,32] = H1 @ W2 + b2, relu, @aow ===
    {
        const int nt = w & 3;           // n-tile (8 of 32 cols)
        const int q  = w >> 2;          // m-quarter
        const int ncol = nt * 8 + l4;
        unsigned int B0[8], B1[8];
#pragma unroll
        for (int kk = 0; kk < 8; ++kk) {
            B0[kk] = f2tf(sm[OFF_W2 + (kk * 8 + lm) * 36 + ncol]);
            B1[kk] = f2tf(sm[OFF_W2 + (kk * 8 + lm + 4) * 36 + ncol]);
        }
        const float bc0 = sm[OFF_AB2 + nt * 8 + 2 * lm];
        const float bc1 = sm[OFF_AB2 + nt * 8 + 2 * lm + 1];
        const float aw0 = sm[OFF_AOW + nt * 8 + 2 * lm];
        const float aw1v = sm[OFF_AOW + nt * 8 + 2 * lm + 1];
        const int beg4[4] = {0, 4, 7, 10};
        const int end4[4] = {4, 7, 10, 13};
        for (int mt = beg4[q]; mt < end4[q]; ++mt) {
            float c0 = bc0, c1 = bc1, c2 = bc0, c3 = bc1;
            const int arow = mt * 16 + l4;
            const float* ab = sm + OFF_H1 + arow * PH + lm;
#pragma unroll
            for (int kk = 0; kk < 8; ++kk) {
                unsigned int a0 = f2tf(ab[kk * 8]);
                unsigned int a1 = f2tf(ab[8 * PH + kk * 8]);
                unsigned int a2 = f2tf(ab[kk * 8 + 4]);
                unsigned int a3 = f2tf(ab[8 * PH + kk * 8 + 4]);
                mma_tf32(c0, c1, c2, c3, a0, a1, a2, a3, B0[kk], B1[kk]);
            }
            float p01 = fmaf(fmaxf(c0, 0.f), aw0, fmaxf(c1, 0.f) * aw1v);
            float p23 = fmaf(fmaxf(c2, 0.f), aw0, fmaxf(c3, 0.f) * aw1v);
            p01 += __shfl_xor_sync(0xffffffffu, p01, 1);
            p01 += __shfl_xor_sync(0xffffffffu, p01, 2);
            p23 += __shfl_xor_sync(0xffffffffu, p23, 1);
            p23 += __shfl_xor_sync(0xffffffffu, p23, 2);
            if (lm == 0) {
                sm[OFF_SCP + nt * 208 + arow]     = p01;
                sm[OFF_SCP + nt * 208 + arow + 8] = p23;
            }
        }
    }
    __syncthreads();

    // ---- combine score partials + mask ----
    const float aob0 = aob[0];
    if (tid < T_) {
        float s = sm[OFF_SCP + tid] + sm[OFF_SCP + 208 + tid] +
                  sm[OFF_SCP + 416 + tid] + sm[OFF_SCP + 624 + tid] + aob0;
        sm[OFF_SC + tid] = (mask[b * T_ + tid] != 0) ? s : -1e9f;
    }
    __syncthreads();

    // ---- softmax over 200 scores (16 warps; inactive lanes neutral) ----
    float v = (tid < T_) ? sm[OFF_SC + tid] : -1e30f;
    float m = v;
    m = fmaxf(m, __shfl_xor_sync(0xffffffffu, m, 16));
    m = fmaxf(m, __shfl_xor_sync(0xffffffffu, m, 8));
    m = fmaxf(m, __shfl_xor_sync(0xffffffffu, m, 4));
    m = fmaxf(m, __shfl_xor_sync(0xffffffffu, m, 2));
    m = fmaxf(m, __shfl_xor_sync(0xffffffffu, m, 1));
    if (l == 0) sm[OFF_WRED + w] = m;
    __syncthreads();
    if (tid == 0) {
        float mm = sm[OFF_WRED];
#pragma unroll
        for (int i = 1; i < 16; ++i) mm = fmaxf(mm, sm[OFF_WRED + i]);
        sm[OFF_WRED + 16] = mm;
    }
    __syncthreads();
    m = sm[OFF_WRED + 16];
    float e = (tid < T_) ? __expf(v - m) : 0.f;
    float s = e;
    s += __shfl_xor_sync(0xffffffffu, s, 16);
    s += __shfl_xor_sync(0xffffffffu, s, 8);
    s += __shfl_xor_sync(0xffffffffu, s, 4);
    s += __shfl_xor_sync(0xffffffffu, s, 2);
    s += __shfl_xor_sync(0xffffffffu, s, 1);
    if (l == 0) sm[OFF_WRED + 17 + w] = s;
    __syncthreads();
    if (tid == 0) {
        float ss = 0.f;
#pragma unroll
        for (int i = 0; i < 16; ++i) ss += sm[OFF_WRED + 17 + i];
        sm[OFF_WRED + 33] = 1.f / ss;
    }
    __syncthreads();
    float inv = sm[OFF_WRED + 33];
    if (tid < T_) sm[OFF_SC + tid] = e * inv;
    __syncthreads();

    // ---- interest = sum_t w[t] * hist[t][:] (fp32, 8 groups x 25 tokens) ----
    {
        int j = tid & 63, g = tid >> 6;
        float acc = 0.f;
        for (int t = g * 25; t < (g + 1) * 25; ++t)
            acc = fmaf(sm[OFF_SC + t], sm[OFF_HIST + t * PH + j], acc);
        sm[OFF_RED + g * 64 + j] = acc;
    }
    __syncthreads();
    if (tid < 64) {
        float iv = 0.f;
#pragma unroll
        for (int g = 0; g < 8; ++g) iv += sm[OFF_RED + g * 64 + tid];
        g_inter[b * 64 + tid] = iv;
    }
}

// ============================================================
// final MLP: [B,128] -> 256 -> 128 -> 1 (unchanged, fp32)
// ============================================================
#define C_XS   0        // 16*128 = 2048
#define C_WT   2048     // 8192 (reused: 32x256 then 32x128 tiles)
#define C_G1   10240    // 16*256 = 4096
#define C_MB1  14336    // 256
#define C_MB2  14592    // 128
#define C_OW   14720    // 128
#define SMEM_C_FLOATS 14848
#define SMEM_C_BYTES  (SMEM_C_FLOATS * 4)

__global__ __launch_bounds__(256) void din_final(
    const float* __restrict__ mw1, const float* __restrict__ mb1,
    const float* __restrict__ mw2, const float* __restrict__ mb2,
    const float* __restrict__ ow,  const float* __restrict__ ob,
    float* __restrict__ out) {
    extern __shared__ float sm[];
    const int tid = threadIdx.x;
    const int b0  = blockIdx.x * 16;
    const int r   = tid >> 4;
    const int jg  = tid & 15;

    for (int idx = tid; idx < 16 * 128; idx += 256) {
        int rr = idx >> 7, c = idx & 127;
        sm[C_XS + idx] = (c < 64) ? g_item[(b0 + rr) * 64 + c]
                                  : g_inter[(b0 + rr) * 64 + (c - 64)];
    }
    sm[C_MB1 + tid] = mb1[tid];
    if (tid < 128) { sm[C_MB2 + tid] = mb2[tid]; sm[C_OW + tid] = ow[tid]; }
    __syncthreads();

    float a1[16];
#pragma unroll
    for (int jj = 0; jj < 4; ++jj)
#pragma unroll
        for (int c = 0; c < 4; ++c)
            a1[jj * 4 + c] = sm[C_MB1 + jg * 4 + jj * 64 + c];

    for (int kt = 0; kt < 4; ++kt) {
        for (int idx = tid; idx < 32 * 256; idx += 256) {
            int row = idx >> 8, col = idx & 255;
            sm[C_WT + idx] = mw1[(kt * 32 + row) * 256 + col];
        }
        __syncthreads();
        const float4* wbase = (const float4*)(sm + C_WT);
#pragma unroll
        for (int k = 0; k < 32; ++k) {
            float xk = sm[C_XS + r * 128 + kt * 32 + k];
            float4 w0 = wbase[k * 64 + jg];
            float4 w1 = wbase[k * 64 + 16 + jg];
            float4 w2 = wbase[k * 64 + 32 + jg];
            float4 w3 = wbase[k * 64 + 48 + jg];
            a1[0]  = fmaf(xk, w0.x, a1[0]);  a1[1]  = fmaf(xk, w0.y, a1[1]);
            a1[2]  = fmaf(xk, w0.z, a1[2]);  a1[3]  = fmaf(xk, w0.w, a1[3]);
            a1[4]  = fmaf(xk, w1.x, a1[4]);  a1[5]  = fmaf(xk, w1.y, a1[5]);
            a1[6]  = fmaf(xk, w1.z, a1[6]);  a1[7]  = fmaf(xk, w1.w, a1[7]);
            a1[8]  = fmaf(xk, w2.x, a1[8]);  a1[9]  = fmaf(xk, w2.y, a1[9]);
            a1[10] = fmaf(xk, w2.z, a1[10]); a1[11] = fmaf(xk, w2.w, a1[11]);
            a1[12] = fmaf(xk, w3.x, a1[12]); a1[13] = fmaf(xk, w3.y, a1[13]);
            a1[14] = fmaf(xk, w3.z, a1[14]); a1[15] = fmaf(xk, w3.w, a1[15]);
        }
        __syncthreads();
    }
#pragma unroll
    for (int jj = 0; jj < 4; ++jj)
#pragma unroll
        for (int c = 0; c < 4; ++c)
            sm[C_G1 + r * 256 + jg * 4 + jj * 64 + c] = fmaxf(a1[jj * 4 + c], 0.f);
    __syncthreads();

    float a2[8];
#pragma unroll
    for (int jj = 0; jj < 2; ++jj)
#pragma unroll
        for (int c = 0; c < 4; ++c)
            a2[jj * 4 + c] = sm[C_MB2 + jg * 4 + jj * 64 + c];

    for (int kt = 0; kt < 8; ++kt) {
        for (int idx = tid; idx < 32 * 128; idx += 256) {
            int row = idx >> 7, col = idx & 127;
            sm[C_WT + idx] = mw2[(kt * 32 + row) * 128 + col];
        }
        __syncthreads();
        const float4* wbase = (const float4*)(sm + C_WT);
#pragma unroll
        for (int k = 0; k < 32; ++k) {
            float gk = sm[C_G1 + r * 256 + kt * 32 + k];
            float4 w0 = wbase[k * 32 + jg];
            float4 w1 = wbase[k * 32 + 16 + jg];
            a2[0] = fmaf(gk, w0.x, a2[0]); a2[1] = fmaf(gk, w0.y, a2[1]);
            a2[2] = fmaf(gk, w0.z, a2[2]); a2[3] = fmaf(gk, w0.w, a2[3]);
            a2[4] = fmaf(gk, w1.x, a2[4]); a2[5] = fmaf(gk, w1.y, a2[5]);
            a2[6] = fmaf(gk, w1.z, a2[6]); a2[7] = fmaf(gk, w1.w, a2[7]);
        }
        __syncthreads();
    }

    float p = 0.f;
#pragma unroll
    for (int jj = 0; jj < 2; ++jj)
#pragma unroll
        for (int c = 0; c < 4; ++c) {
            int j = jg * 4 + jj * 64 + c;
            p = fmaf(fmaxf(a2[jj * 4 + c], 0.f), sm[C_OW + j], p);
        }
    p += __shfl_xor_sync(0xffffffffu, p, 8);
    p += __shfl_xor_sync(0xffffffffu, p, 4);
    p += __shfl_xor_sync(0xffffffffu, p, 2);
    p += __shfl_xor_sync(0xffffffffu, p, 1);
    if (jg == 0) out[b0 + r] = p + ob[0];
}

// ============================================================
// launch
// ============================================================
extern "C" void kernel_launch(void* const* d_in, const int* in_sizes, int n_in,
                              void* d_out, int out_size) {
    const int*   target  = (const int*)d_in[0];
    const int*   hist_id = (const int*)d_in[1];
    const int*   mask    = (const int*)d_in[2];     // bool promoted; test != 0
    const float* table   = (const float*)d_in[3];
    const float* aw1     = (const float*)d_in[4];
    const float* ab1     = (const float*)d_in[5];
    const float* aw2     = (const float*)d_in[6];
    const float* ab2     = (const float*)d_in[7];
    const float* aow     = (const float*)d_in[8];
    const float* aob     = (const float*)d_in[9];
    const float* mw1     = (const float*)d_in[10];
    const float* mb1     = (const float*)d_in[11];
    const float* mw2     = (const float*)d_in[12];
    const float* mb2     = (const float*)d_in[13];
    const float* ow      = (const float*)d_in[14];
    const float* ob      = (const float*)d_in[15];
    float* out = (float*)d_out;

    cudaFuncSetAttribute(din_main, cudaFuncAttributeMaxDynamicSharedMemorySize, SMEM_B_BYTES);
    cudaFuncSetAttribute(din_final, cudaFuncAttributeMaxDynamicSharedMemorySize, SMEM_C_BYTES);

    prep_weights<<<8, 512>>>(aw1);
    prep_batch<<<B_, 64>>>(target, table, ab1);
    din_main<<<B_, 512, SMEM_B_BYTES>>>(hist_id, mask, table, aw2, ab2, aow, aob);
    din_final<<<B_ / 16, 256, SMEM_C_BYTES>>>(mw1, mb1, mw2, mb2, ow, ob, out);
}

// round 4
// speedup vs baseline: 1.9552x; 1.3378x over previous
#include <cuda_runtime.h>
#include <cuda_bf16.h>
#include <math.h>

// Problem constants
#define B_  4096
#define T_  200
#define E_  64
#define A1_ 64
#define A2_ 32
#define M1_ 256
#define M2_ 128

// -------- device scratch (no allocations allowed) --------
__device__ float g_Wh[64 * 64];     // aw1[0:64] + aw1[128:192]
__device__ float g_Wq[64 * 64];     // aw1[64:128] - aw1[128:192]
__device__ float g_Wp[64 * 64];     // aw1[192:256]
__device__ float g_qb[B_ * 64];     // per-batch layer1 bias: ab1 + item @ Wq
__device__ float g_item[B_ * 64];   // gathered item embeddings
__device__ float g_inter[B_ * 64];  // interest vectors

// ---- tf32 helpers ----
__device__ __forceinline__ unsigned int f2tf(float f) {
    unsigned int r;
    asm("cvt.rna.tf32.f32 %0, %1;" : "=r"(r) : "f"(f));
    return r;
}
__device__ __forceinline__ void mma_tf32(
    float& c0, float& c1, float& c2, float& c3,
    unsigned int a0, unsigned int a1, unsigned int a2, unsigned int a3,
    unsigned int b0, unsigned int b1) {
    asm("mma.sync.aligned.m16n8k8.row.col.f32.tf32.tf32.f32 "
        "{%0,%1,%2,%3},{%4,%5,%6,%7},{%8,%9},{%0,%1,%2,%3};"
        : "+f"(c0), "+f"(c1), "+f"(c2), "+f"(c3)
        : "r"(a0), "r"(a1), "r"(a2), "r"(a3), "r"(b0), "r"(b1));
}

// ============================================================
// prep 1: fold aw1 into Wh / Wq / Wp
// ============================================================
__global__ void prep_weights(const float* __restrict__ aw1) {
    int idx = blockIdx.x * blockDim.x + threadIdx.x;
    if (idx >= 64 * 64) return;
    int j = idx & 63, k = idx >> 6;
    float a = aw1[k * 64 + j];
    float b = aw1[(64 + k) * 64 + j];
    float c = aw1[(128 + k) * 64 + j];
    float d = aw1[(192 + k) * 64 + j];
    g_Wh[k * 64 + j] = a + c;
    g_Wq[k * 64 + j] = b - c;
    g_Wp[k * 64 + j] = d;
}

// ============================================================
// prep 2: gather item embedding, compute per-batch qb = ab1 + item @ Wq
// ============================================================
__global__ void prep_batch(const int* __restrict__ target,
                           const float* __restrict__ table,
                           const float* __restrict__ ab1) {
    __shared__ float it[64];
    int b = blockIdx.x;
    int j = threadIdx.x;
    it[j] = table[(size_t)target[b] * 64 + j];
    __syncthreads();
    float acc = ab1[j];
#pragma unroll
    for (int k = 0; k < 64; ++k)
        acc = fmaf(it[k], g_Wq[k * 64 + j], acc);
    g_qb[b * 64 + j] = acc;
    g_item[b * 64 + j] = it[j];
}

// ============================================================
// main kernel: one CTA (512 threads) per batch element.
// Layers 1+2 FUSED on tf32 tensor cores: layer-1 C fragments are
// relu'd and transposed to layer-2 A fragments via quad shuffles.
// No H1 buffer -> smem 87KB -> 2 CTAs/SM.
// ============================================================
#define PH 68    // HIST/WC pitch (floats): bank-conflict-free fragment loads
// smem layout (float offsets)
#define OFF_HIST  0        // 208*68 = 14144
#define OFF_WCU   14144    // 64*68  = 4352 -> 18496 (folded layer1 W, tf32 bits)
#define OFF_W2U   18496    // 64*36  = 2304 -> 20800 (aw2, tf32 bits, pitch 36)
#define OFF_QV    20800    // 64
#define OFF_QB    20864    // 64
#define OFF_AB2   20928    // 32
#define OFF_AOW   20960    // 32
#define OFF_SC    20992    // 208 -> 21200
#define OFF_WRED  21200    // 48  -> 21248
#define OFF_RED   21248    // 512 -> 21760
#define SMEM_B_FLOATS 21760
#define SMEM_B_BYTES  (SMEM_B_FLOATS * 4)

__global__ __launch_bounds__(512, 2) void din_main(
    const int* __restrict__ hist_id,
    const int* __restrict__ mask,        // bool promoted to 4-byte; test != 0
    const float* __restrict__ table,
    const float* __restrict__ aw2,
    const float* __restrict__ ab2,
    const float* __restrict__ aow,
    const float* __restrict__ aob) {
    extern __shared__ float sm[];
    unsigned int* smu = (unsigned int*)sm;
    const int b   = blockIdx.x;
    const int tid = threadIdx.x;
    const int w   = tid >> 5;
    const int l   = tid & 31;
    const int l4  = l >> 2;   // 0..7
    const int lm  = l & 3;    // 0..3

    // --- stage small vectors ---
    if (tid < 64)        sm[OFF_QV + tid]        = g_item[b * 64 + tid];
    else if (tid < 128)  sm[OFF_QB + tid - 64]   = g_qb[b * 64 + tid - 64];
    else if (tid < 160)  sm[OFF_AB2 + tid - 128] = ab2[tid - 128];
    else if (tid < 192)  sm[OFF_AOW + tid - 160] = aow[tid - 160];
    __syncthreads();   // qv needed for Wc fold

    // --- fold Wc[k][n] = Wh + q[k]*Wp, store as tf32 bits (pitch 68) ---
    for (int idx = tid; idx < 64 * 64; idx += 512) {
        int n = idx & 63, k = idx >> 6;
        smu[OFF_WCU + k * PH + n] =
            f2tf(fmaf(sm[OFF_QV + k], g_Wp[k * 64 + n], g_Wh[k * 64 + n]));
    }
    // --- stage aw2 as tf32 bits [k][n] pitch 36 ---
    for (int idx = tid; idx < 64 * 32; idx += 512) {
        int n = idx & 31, k = idx >> 5;
        smu[OFF_W2U + k * 36 + n] = f2tf(aw2[k * 32 + n]);
    }
    // --- gather history embeddings (float4; row stride 17 float4) ---
    {
        const float4* tab4 = (const float4*)table;
        float4* hist4 = (float4*)(sm + OFF_HIST);
        for (int idx = tid; idx < T_ * 16; idx += 512) {
            int t = idx >> 4, v = idx & 15;
            hist4[t * 17 + v] = tab4[(size_t)hist_id[b * T_ + t] * 16 + v];
        }
        for (int idx = tid; idx < 8 * 17; idx += 512) {
            int t = 200 + idx / 17, v = idx % 17;
            hist4[t * 17 + v] = make_float4(0.f, 0.f, 0.f, 0.f);
        }
    }
    __syncthreads();

    // ============ fused attention MLP: warp w < 13 owns rows [16w, 16w+16) ====
    if (w < 13) {
        const int mt = w;
        const float aob0 = aob[0];

        // hoist A fragments (HIST rows, tf32): 32 regs
        unsigned int au[32];
        {
            const float* abase = sm + OFF_HIST + (mt * 16 + l4) * PH + lm;
#pragma unroll
            for (int k = 0; k < 8; ++k) {
                au[4 * k + 0] = f2tf(abase[k * 8]);
                au[4 * k + 1] = f2tf(abase[8 * PH + k * 8]);
                au[4 * k + 2] = f2tf(abase[k * 8 + 4]);
                au[4 * k + 3] = f2tf(abase[8 * PH + k * 8 + 4]);
            }
        }

        // layer-2 accumulators (4 n-tiles of 8), bias-initialized
        float d0[4], d1[4], d2[4], d3[4];
#pragma unroll
        for (int nt2 = 0; nt2 < 4; ++nt2) {
            float bb0 = sm[OFF_AB2 + nt2 * 8 + 2 * lm];
            float bb1 = sm[OFF_AB2 + nt2 * 8 + 2 * lm + 1];
            d0[nt2] = bb0; d1[nt2] = bb1; d2[nt2] = bb0; d3[nt2] = bb1;
        }

        const unsigned int* wc_col = smu + OFF_WCU + lm * PH;
        const unsigned int* w2_col = smu + OFF_W2U + lm * 36 + l4;

        for (int kk = 0; kk < 8; ++kk) {     // layer1 n-tile == layer2 k-chunk
            // ---- layer 1: c = HIST_tile @ Wc[:, kk*8..+8) + qb ----
            float c0 = sm[OFF_QB + kk * 8 + 2 * lm];
            float c1 = sm[OFF_QB + kk * 8 + 2 * lm + 1];
            float c2 = c0, c3 = c1;
            const unsigned int* wcb = wc_col + kk * 8 + l4;
#pragma unroll
            for (int k = 0; k < 8; ++k) {
                unsigned int b0v = wcb[k * 8 * PH];
                unsigned int b1v = wcb[k * 8 * PH + 4 * PH];
                mma_tf32(c0, c1, c2, c3,
                         au[4 * k], au[4 * k + 1], au[4 * k + 2], au[4 * k + 3],
                         b0v, b1v);
            }
            c0 = fmaxf(c0, 0.f); c1 = fmaxf(c1, 0.f);
            c2 = fmaxf(c2, 0.f); c3 = fmaxf(c3, 0.f);

            // ---- transpose C frag -> layer2 A frag (quad shuffles) ----
            int src1 = (l & ~3) + (lm >> 1);
            int src2 = src1 + 2;
            float v0a = __shfl_sync(0xffffffffu, c0, src1);
            float v1a = __shfl_sync(0xffffffffu, c1, src1);
            float v2a = __shfl_sync(0xffffffffu, c2, src1);
            float v3a = __shfl_sync(0xffffffffu, c3, src1);
            float v0b = __shfl_sync(0xffffffffu, c0, src2);
            float v1b = __shfl_sync(0xffffffffu, c1, src2);
            float v2b = __shfl_sync(0xffffffffu, c2, src2);
            float v3b = __shfl_sync(0xffffffffu, c3, src2);
            bool hi = (lm & 1);
            unsigned int a0 = f2tf(hi ? v1a : v0a);   // (row l4,   k=lm)
            unsigned int a1 = f2tf(hi ? v3a : v2a);   // (row l4+8, k=lm)
            unsigned int a2 = f2tf(hi ? v1b : v0b);   // (row l4,   k=lm+4)
            unsigned int a3 = f2tf(hi ? v3b : v2b);   // (row l4+8, k=lm+4)

            // ---- layer 2 accumulate: 4 n-tiles ----
            const unsigned int* w2b = w2_col + kk * 8 * 36;
#pragma unroll
            for (int nt2 = 0; nt2 < 4; ++nt2) {
                unsigned int b0v = w2b[nt2 * 8];
                unsigned int b1v = w2b[nt2 * 8 + 4 * 36];
                mma_tf32(d0[nt2], d1[nt2], d2[nt2], d3[nt2],
                         a0, a1, a2, a3, b0v, b1v);
            }
        }

        // ---- relu + score dot with aow, quad-reduce, write masked score ----
        float p01 = 0.f, p23 = 0.f;
#pragma unroll
        for (int nt2 = 0; nt2 < 4; ++nt2) {
            float w0 = sm[OFF_AOW + nt2 * 8 + 2 * lm];
            float w1 = sm[OFF_AOW + nt2 * 8 + 2 * lm + 1];
            p01 = fmaf(fmaxf(d0[nt2], 0.f), w0, fmaf(fmaxf(d1[nt2], 0.f), w1, p01));
            p23 = fmaf(fmaxf(d2[nt2], 0.f), w0, fmaf(fmaxf(d3[nt2], 0.f), w1, p23));
        }
        p01 += __shfl_xor_sync(0xffffffffu, p01, 1);
        p01 += __shfl_xor_sync(0xffffffffu, p01, 2);
        p23 += __shfl_xor_sync(0xffffffffu, p23, 1);
        p23 += __shfl_xor_sync(0xffffffffu, p23, 2);
        if (lm == 0) {
            int r0 = mt * 16 + l4;
            int r1 = r0 + 8;
            if (r0 < T_)
                sm[OFF_SC + r0] = (mask[b * T_ + r0] != 0) ? p01 + aob0 : -1e9f;
            if (r1 < T_)
                sm[OFF_SC + r1] = (mask[b * T_ + r1] != 0) ? p23 + aob0 : -1e9f;
        }
    }
    __syncthreads();

    // ---- softmax over 200 scores ----
    float v = (tid < T_) ? sm[OFF_SC + tid] : -1e30f;
    float m = v;
    m = fmaxf(m, __shfl_xor_sync(0xffffffffu, m, 16));
    m = fmaxf(m, __shfl_xor_sync(0xffffffffu, m, 8));
    m = fmaxf(m, __shfl_xor_sync(0xffffffffu, m, 4));
    m = fmaxf(m, __shfl_xor_sync(0xffffffffu, m, 2));
    m = fmaxf(m, __shfl_xor_sync(0xffffffffu, m, 1));
    if (l == 0) sm[OFF_WRED + w] = m;
    __syncthreads();
    if (tid == 0) {
        float mm = sm[OFF_WRED];
#pragma unroll
        for (int i = 1; i < 16; ++i) mm = fmaxf(mm, sm[OFF_WRED + i]);
        sm[OFF_WRED + 16] = mm;
    }
    __syncthreads();
    m = sm[OFF_WRED + 16];
    float e = (tid < T_) ? __expf(v - m) : 0.f;
    float s = e;
    s += __shfl_xor_sync(0xffffffffu, s, 16);
    s += __shfl_xor_sync(0xffffffffu, s, 8);
    s += __shfl_xor_sync(0xffffffffu, s, 4);
    s += __shfl_xor_sync(0xffffffffu, s, 2);
    s += __shfl_xor_sync(0xffffffffu, s, 1);
    if (l == 0) sm[OFF_WRED + 17 + w] = s;
    __syncthreads();
    if (tid == 0) {
        float ss = 0.f;
#pragma unroll
        for (int i = 0; i < 16; ++i) ss += sm[OFF_WRED + 17 + i];
        sm[OFF_WRED + 33] = 1.f / ss;
    }
    __syncthreads();
    float inv = sm[OFF_WRED + 33];
    if (tid < T_) sm[OFF_SC + tid] = e * inv;
    __syncthreads();

    // ---- interest = sum_t w[t] * hist[t][:] (fp32, 8 groups x 25 tokens) ----
    {
        int j = tid & 63, g = tid >> 6;
        float acc = 0.f;
        for (int t = g * 25; t < (g + 1) * 25; ++t)
            acc = fmaf(sm[OFF_SC + t], sm[OFF_HIST + t * PH + j], acc);
        sm[OFF_RED + g * 64 + j] = acc;
    }
    __syncthreads();
    if (tid < 64) {
        float iv = 0.f;
#pragma unroll
        for (int g = 0; g < 8; ++g) iv += sm[OFF_RED + g * 64 + tid];
        g_inter[b * 64 + tid] = iv;
    }
}

// ============================================================
// final MLP: [B,128] -> 256 -> 128 -> 1 (unchanged, fp32)
// ============================================================
#define C_XS   0        // 16*128 = 2048
#define C_WT   2048     // 8192 (reused: 32x256 then 32x128 tiles)
#define C_G1   10240    // 16*256 = 4096
#define C_MB1  14336    // 256
#define C_MB2  14592    // 128
#define C_OW   14720    // 128
#define SMEM_C_FLOATS 14848
#define SMEM_C_BYTES  (SMEM_C_FLOATS * 4)

__global__ __launch_bounds__(256) void din_final(
    const float* __restrict__ mw1, const float* __restrict__ mb1,
    const float* __restrict__ mw2, const float* __restrict__ mb2,
    const float* __restrict__ ow,  const float* __restrict__ ob,
    float* __restrict__ out) {
    extern __shared__ float sm[];
    const int tid = threadIdx.x;
    const int b0  = blockIdx.x * 16;
    const int r   = tid >> 4;
    const int jg  = tid & 15;

    for (int idx = tid; idx < 16 * 128; idx += 256) {
        int rr = idx >> 7, c = idx & 127;
        sm[C_XS + idx] = (c < 64) ? g_item[(b0 + rr) * 64 + c]
                                  : g_inter[(b0 + rr) * 64 + (c - 64)];
    }
    sm[C_MB1 + tid] = mb1[tid];
    if (tid < 128) { sm[C_MB2 + tid] = mb2[tid]; sm[C_OW + tid] = ow[tid]; }
    __syncthreads();

    float a1[16];
#pragma unroll
    for (int jj = 0; jj < 4; ++jj)
#pragma unroll
        for (int c = 0; c < 4; ++c)
            a1[jj * 4 + c] = sm[C_MB1 + jg * 4 + jj * 64 + c];

    for (int kt = 0; kt < 4; ++kt) {
        for (int idx = tid; idx < 32 * 256; idx += 256) {
            int row = idx >> 8, col = idx & 255;
            sm[C_WT + idx] = mw1[(kt * 32 + row) * 256 + col];
        }
        __syncthreads();
        const float4* wbase = (const float4*)(sm + C_WT);
#pragma unroll
        for (int k = 0; k < 32; ++k) {
            float xk = sm[C_XS + r * 128 + kt * 32 + k];
            float4 w0 = wbase[k * 64 + jg];
            float4 w1 = wbase[k * 64 + 16 + jg];
            float4 w2 = wbase[k * 64 + 32 + jg];
            float4 w3 = wbase[k * 64 + 48 + jg];
            a1[0]  = fmaf(xk, w0.x, a1[0]);  a1[1]  = fmaf(xk, w0.y, a1[1]);
            a1[2]  = fmaf(xk, w0.z, a1[2]);  a1[3]  = fmaf(xk, w0.w, a1[3]);
            a1[4]  = fmaf(xk, w1.x, a1[4]);  a1[5]  = fmaf(xk, w1.y, a1[5]);
            a1[6]  = fmaf(xk, w1.z, a1[6]);  a1[7]  = fmaf(xk, w1.w, a1[7]);
            a1[8]  = fmaf(xk, w2.x, a1[8]);  a1[9]  = fmaf(xk, w2.y, a1[9]);
            a1[10] = fmaf(xk, w2.z, a1[10]); a1[11] = fmaf(xk, w2.w, a1[11]);
            a1[12] = fmaf(xk, w3.x, a1[12]); a1[13] = fmaf(xk, w3.y, a1[13]);
            a1[14] = fmaf(xk, w3.z, a1[14]); a1[15] = fmaf(xk, w3.w, a1[15]);
        }
        __syncthreads();
    }
#pragma unroll
    for (int jj = 0; jj < 4; ++jj)
#pragma unroll
        for (int c = 0; c < 4; ++c)
            sm[C_G1 + r * 256 + jg * 4 + jj * 64 + c] = fmaxf(a1[jj * 4 + c], 0.f);
    __syncthreads();

    float a2[8];
#pragma unroll
    for (int jj = 0; jj < 2; ++jj)
#pragma unroll
        for (int c = 0; c < 4; ++c)
            a2[jj * 4 + c] = sm[C_MB2 + jg * 4 + jj * 64 + c];

    for (int kt = 0; kt < 8; ++kt) {
        for (int idx = tid; idx < 32 * 128; idx += 256) {
            int row = idx >> 7, col = idx & 127;
            sm[C_WT + idx] = mw2[(kt * 32 + row) * 128 + col];
        }
        __syncthreads();
        const float4* wbase = (const float4*)(sm + C_WT);
#pragma unroll
        for (int k = 0; k < 32; ++k) {
            float gk = sm[C_G1 + r * 256 + kt * 32 + k];
            float4 w0 = wbase[k * 32 + jg];
            float4 w1 = wbase[k * 32 + 16 + jg];
            a2[0] = fmaf(gk, w0.x, a2[0]); a2[1] = fmaf(gk, w0.y, a2[1]);
            a2[2] = fmaf(gk, w0.z, a2[2]); a2[3] = fmaf(gk, w0.w, a2[3]);
            a2[4] = fmaf(gk, w1.x, a2[4]); a2[5] = fmaf(gk, w1.y, a2[5]);
            a2[6] = fmaf(gk, w1.z, a2[6]); a2[7] = fmaf(gk, w1.w, a2[7]);
        }
        __syncthreads();
    }

    float p = 0.f;
#pragma unroll
    for (int jj = 0; jj < 2; ++jj)
#pragma unroll
        for (int c = 0; c < 4; ++c) {
            int j = jg * 4 + jj * 64 + c;
            p = fmaf(fmaxf(a2[jj * 4 + c], 0.f), sm[C_OW + j], p);
        }
    p += __shfl_xor_sync(0xffffffffu, p, 8);
    p += __shfl_xor_sync(0xffffffffu, p, 4);
    p += __shfl_xor_sync(0xffffffffu, p, 2);
    p += __shfl_xor_sync(0xffffffffu, p, 1);
    if (jg == 0) out[b0 + r] = p + ob[0];
}

// ============================================================
// launch
// ============================================================
extern "C" void kernel_launch(void* const* d_in, const int* in_sizes, int n_in,
                              void* d_out, int out_size) {
    const int*   target  = (const int*)d_in[0];
    const int*   hist_id = (const int*)d_in[1];
    const int*   mask    = (const int*)d_in[2];     // bool promoted; test != 0
    const float* table   = (const float*)d_in[3];
    const float* aw1     = (const float*)d_in[4];
    const float* ab1     = (const float*)d_in[5];
    const float* aw2     = (const float*)d_in[6];
    const float* ab2     = (const float*)d_in[7];
    const float* aow     = (const float*)d_in[8];
    const float* aob     = (const float*)d_in[9];
    const float* mw1     = (const float*)d_in[10];
    const float* mb1     = (const float*)d_in[11];
    const float* mw2     = (const float*)d_in[12];
    const float* mb2     = (const float*)d_in[13];
    const float* ow      = (const float*)d_in[14];
    const float* ob      = (const float*)d_in[15];
    float* out = (float*)d_out;

    cudaFuncSetAttribute(din_main, cudaFuncAttributeMaxDynamicSharedMemorySize, SMEM_B_BYTES);
    cudaFuncSetAttribute(din_final, cudaFuncAttributeMaxDynamicSharedMemorySize, SMEM_C_BYTES);

    prep_weights<<<8, 512>>>(aw1);
    prep_batch<<<B_, 64>>>(target, table, ab1);
    din_main<<<B_, 512, SMEM_B_BYTES>>>(hist_id, mask, table, aw2, ab2, aow, aob);
    din_final<<<B_ / 16, 256, SMEM_C_BYTES>>>(mw1, mb1, mw2, mb2, ow, ob, out);
}

// round 5
// speedup vs baseline: 2.0800x; 1.0638x over previous
#include <cuda_runtime.h>
#include <cuda_bf16.h>
#include <math.h>

// Problem constants
#define B_  4096
#define T_  200
#define E_  64
#define A1_ 64
#define A2_ 32
#define M1_ 256
#define M2_ 128

// -------- device scratch (no allocations allowed) --------
__device__ float g_Wh[64 * 64];     // aw1[0:64] + aw1[128:192]
__device__ float g_Wq[64 * 64];     // aw1[64:128] - aw1[128:192]
__device__ float g_Wp[64 * 64];     // aw1[192:256]
__device__ float g_inter[B_ * 64];  // interest vectors

// ---- tf32 helpers ----
__device__ __forceinline__ unsigned int f2tf(float f) {
    unsigned int r;
    asm("cvt.rna.tf32.f32 %0, %1;" : "=r"(r) : "f"(f));
    return r;
}
__device__ __forceinline__ void mma_tf32(
    float& c0, float& c1, float& c2, float& c3,
    unsigned int a0, unsigned int a1, unsigned int a2, unsigned int a3,
    unsigned int b0, unsigned int b1) {
    asm("mma.sync.aligned.m16n8k8.row.col.f32.tf32.tf32.f32 "
        "{%0,%1,%2,%3},{%4,%5,%6,%7},{%8,%9},{%0,%1,%2,%3};"
        : "+f"(c0), "+f"(c1), "+f"(c2), "+f"(c3)
        : "r"(a0), "r"(a1), "r"(a2), "r"(a3), "r"(b0), "r"(b1));
}

// ============================================================
// prep: fold aw1 into Wh / Wq / Wp
// ============================================================
__global__ void prep_weights(const float* __restrict__ aw1) {
    int idx = blockIdx.x * blockDim.x + threadIdx.x;
    if (idx >= 64 * 64) return;
    int j = idx & 63, k = idx >> 6;
    float a = aw1[k * 64 + j];
    float b = aw1[(64 + k) * 64 + j];
    float c = aw1[(128 + k) * 64 + j];
    float d = aw1[(192 + k) * 64 + j];
    g_Wh[k * 64 + j] = a + c;
    g_Wq[k * 64 + j] = b - c;
    g_Wp[k * 64 + j] = d;
}

// ============================================================
// main kernel: one CTA (512 threads) per batch element.
// Fused tf32 attention MLP, streamlined softmax (6 barriers),
// in-kernel qb, mask prefetch. 2 CTAs/SM.
// ============================================================
#define PH 68
// smem layout (float offsets)
#define OFF_HIST  0        // 208*68 = 14144
#define OFF_WCU   14144    // 4352
#define OFF_W2U   18496    // 2304
#define OFF_QV    20800    // 64
#define OFF_QB    20864    // 64
#define OFF_AB2   20928    // 32
#define OFF_AOW   20960    // 32
#define OFF_SC    20992    // 208
#define OFF_MSK   21200    // 208 (int view)
#define OFF_WRED  21408    // 32: [0:16] warp max, [16:32] warp sum
#define OFF_RED   21440    // 512
#define SMEM_B_FLOATS 21952
#define SMEM_B_BYTES  (SMEM_B_FLOATS * 4)

__global__ __launch_bounds__(512, 2) void din_main(
    const int* __restrict__ hist_id,
    const int* __restrict__ mask,        // bool promoted to 4-byte; test != 0
    const float* __restrict__ table,
    const int* __restrict__ target,
    const float* __restrict__ ab1,
    const float* __restrict__ aw2,
    const float* __restrict__ ab2,
    const float* __restrict__ aow,
    const float* __restrict__ aob) {
    extern __shared__ float sm[];
    unsigned int* smu = (unsigned int*)sm;
    int* smi = (int*)sm;
    const int b   = blockIdx.x;
    const int tid = threadIdx.x;
    const int w   = tid >> 5;
    const int l   = tid & 31;
    const int l4  = l >> 2;   // 0..7
    const int lm  = l & 3;    // 0..3

    // --- stage small vectors + mask prefetch ---
    if (tid < 64)        sm[OFF_QV + tid]       = table[(size_t)target[b] * 64 + tid];
    else if (tid < 96)   sm[OFF_AB2 + tid - 64] = ab2[tid - 64];
    else if (tid < 128)  sm[OFF_AOW + tid - 96] = aow[tid - 96];
    else if (tid < 328)  smi[OFF_MSK + tid - 128] = mask[b * T_ + tid - 128];
    __syncthreads();   // B1: QV ready

    // --- qb[n] = ab1[n] + item @ Wq (one warp pair, overlapped with fold) ---
    if (tid < 64) {
        float acc = ab1[tid];
#pragma unroll 8
        for (int k = 0; k < 64; ++k)
            acc = fmaf(sm[OFF_QV + k], g_Wq[k * 64 + tid], acc);
        sm[OFF_QB + tid] = acc;
    }
    // --- fold Wc[k][n] = Wh + q[k]*Wp, store tf32 bits (pitch 68) ---
    for (int idx = tid; idx < 64 * 64; idx += 512) {
        int n = idx & 63, k = idx >> 6;
        smu[OFF_WCU + k * PH + n] =
            f2tf(fmaf(sm[OFF_QV + k], g_Wp[k * 64 + n], g_Wh[k * 64 + n]));
    }
    // --- aw2 as tf32 bits [k][n] pitch 36 ---
    for (int idx = tid; idx < 64 * 32; idx += 512) {
        int n = idx & 31, k = idx >> 5;
        smu[OFF_W2U + k * 36 + n] = f2tf(aw2[k * 32 + n]);
    }
    // --- gather history embeddings ---
    {
        const float4* tab4 = (const float4*)table;
        float4* hist4 = (float4*)(sm + OFF_HIST);
        for (int idx = tid; idx < T_ * 16; idx += 512) {
            int t = idx >> 4, v = idx & 15;
            hist4[t * 17 + v] = tab4[(size_t)hist_id[b * T_ + t] * 16 + v];
        }
        for (int idx = tid; idx < 8 * 17; idx += 512) {
            int t = 200 + idx / 17, v = idx % 17;
            hist4[t * 17 + v] = make_float4(0.f, 0.f, 0.f, 0.f);
        }
    }
    __syncthreads();   // B2: all operands staged

    // ============ fused attention MLP: warps 0..12 own rows [16w, 16w+16) ====
    if (w < 13) {
        const int mt = w;
        const float aob0 = aob[0];

        unsigned int au[32];
        {
            const float* abase = sm + OFF_HIST + (mt * 16 + l4) * PH + lm;
#pragma unroll
            for (int k = 0; k < 8; ++k) {
                au[4 * k + 0] = f2tf(abase[k * 8]);
                au[4 * k + 1] = f2tf(abase[8 * PH + k * 8]);
                au[4 * k + 2] = f2tf(abase[k * 8 + 4]);
                au[4 * k + 3] = f2tf(abase[8 * PH + k * 8 + 4]);
            }
        }

        float d0[4], d1[4], d2[4], d3[4];
#pragma unroll
        for (int nt2 = 0; nt2 < 4; ++nt2) {
            float bb0 = sm[OFF_AB2 + nt2 * 8 + 2 * lm];
            float bb1 = sm[OFF_AB2 + nt2 * 8 + 2 * lm + 1];
            d0[nt2] = bb0; d1[nt2] = bb1; d2[nt2] = bb0; d3[nt2] = bb1;
        }

        const unsigned int* wc_col = smu + OFF_WCU + lm * PH;
        const unsigned int* w2_col = smu + OFF_W2U + lm * 36 + l4;

        for (int kk = 0; kk < 8; ++kk) {
            float c0 = sm[OFF_QB + kk * 8 + 2 * lm];
            float c1 = sm[OFF_QB + kk * 8 + 2 * lm + 1];
            float c2 = c0, c3 = c1;
            const unsigned int* wcb = wc_col + kk * 8 + l4;
#pragma unroll
            for (int k = 0; k < 8; ++k) {
                unsigned int b0v = wcb[k * 8 * PH];
                unsigned int b1v = wcb[k * 8 * PH + 4 * PH];
                mma_tf32(c0, c1, c2, c3,
                         au[4 * k], au[4 * k + 1], au[4 * k + 2], au[4 * k + 3],
                         b0v, b1v);
            }
            c0 = fmaxf(c0, 0.f); c1 = fmaxf(c1, 0.f);
            c2 = fmaxf(c2, 0.f); c3 = fmaxf(c3, 0.f);

            int src1 = (l & ~3) + (lm >> 1);
            int src2 = src1 + 2;
            float v0a = __shfl_sync(0xffffffffu, c0, src1);
            float v1a = __shfl_sync(0xffffffffu, c1, src1);
            float v2a = __shfl_sync(0xffffffffu, c2, src1);
            float v3a = __shfl_sync(0xffffffffu, c3, src1);
            float v0b = __shfl_sync(0xffffffffu, c0, src2);
            float v1b = __shfl_sync(0xffffffffu, c1, src2);
            float v2b = __shfl_sync(0xffffffffu, c2, src2);
            float v3b = __shfl_sync(0xffffffffu, c3, src2);
            bool hi = (lm & 1);
            unsigned int a0 = f2tf(hi ? v1a : v0a);
            unsigned int a1 = f2tf(hi ? v3a : v2a);
            unsigned int a2 = f2tf(hi ? v1b : v0b);
            unsigned int a3 = f2tf(hi ? v3b : v2b);

            const unsigned int* w2b = w2_col + kk * 8 * 36;
#pragma unroll
            for (int nt2 = 0; nt2 < 4; ++nt2) {
                unsigned int b0v = w2b[nt2 * 8];
                unsigned int b1v = w2b[nt2 * 8 + 4 * 36];
                mma_tf32(d0[nt2], d1[nt2], d2[nt2], d3[nt2],
                         a0, a1, a2, a3, b0v, b1v);
            }
        }

        float p01 = 0.f, p23 = 0.f;
#pragma unroll
        for (int nt2 = 0; nt2 < 4; ++nt2) {
            float w0 = sm[OFF_AOW + nt2 * 8 + 2 * lm];
            float w1 = sm[OFF_AOW + nt2 * 8 + 2 * lm + 1];
            p01 = fmaf(fmaxf(d0[nt2], 0.f), w0, fmaf(fmaxf(d1[nt2], 0.f), w1, p01));
            p23 = fmaf(fmaxf(d2[nt2], 0.f), w0, fmaf(fmaxf(d3[nt2], 0.f), w1, p23));
        }
        p01 += __shfl_xor_sync(0xffffffffu, p01, 1);
        p01 += __shfl_xor_sync(0xffffffffu, p01, 2);
        p23 += __shfl_xor_sync(0xffffffffu, p23, 1);
        p23 += __shfl_xor_sync(0xffffffffu, p23, 2);
        if (lm == 0) {
            int r0 = mt * 16 + l4;
            int r1 = r0 + 8;
            if (r0 < T_)
                sm[OFF_SC + r0] = (smi[OFF_MSK + r0] != 0) ? p01 + aob0 : -1e9f;
            if (r1 < T_)
                sm[OFF_SC + r1] = (smi[OFF_MSK + r1] != 0) ? p23 + aob0 : -1e9f;
        }
    }
    __syncthreads();   // B3: scores ready

    // ---- softmax (streamlined): warp max -> broadcast max -> exp ----
    float v = (tid < T_) ? sm[OFF_SC + tid] : -1e30f;
    float m = v;
    m = fmaxf(m, __shfl_xor_sync(0xffffffffu, m, 16));
    m = fmaxf(m, __shfl_xor_sync(0xffffffffu, m, 8));
    m = fmaxf(m, __shfl_xor_sync(0xffffffffu, m, 4));
    m = fmaxf(m, __shfl_xor_sync(0xffffffffu, m, 2));
    m = fmaxf(m, __shfl_xor_sync(0xffffffffu, m, 1));
    if (l == 0) sm[OFF_WRED + w] = m;
    __syncthreads();   // B4
    float gm = sm[OFF_WRED + 0];
#pragma unroll
    for (int i = 1; i < 16; ++i) gm = fmaxf(gm, sm[OFF_WRED + i]);
    float e = (tid < T_) ? __expf(v - gm) : 0.f;
    if (tid < T_) sm[OFF_SC + tid] = e;     // unnormalized
    float s = e;
    s += __shfl_xor_sync(0xffffffffu, s, 16);
    s += __shfl_xor_sync(0xffffffffu, s, 8);
    s += __shfl_xor_sync(0xffffffffu, s, 4);
    s += __shfl_xor_sync(0xffffffffu, s, 2);
    s += __shfl_xor_sync(0xffffffffu, s, 1);
    if (l == 0) sm[OFF_WRED + 16 + w] = s;
    __syncthreads();   // B5

    // ---- interest (normalization folded in): 8 groups x 25 tokens ----
    {
        float ss = sm[OFF_WRED + 16];
#pragma unroll
        for (int i = 1; i < 16; ++i) ss += sm[OFF_WRED + 16 + i];
        float inv = 1.f / ss;
        int j = tid & 63, g = tid >> 6;
        float acc = 0.f;
        for (int t = g * 25; t < (g + 1) * 25; ++t)
            acc = fmaf(sm[OFF_SC + t], sm[OFF_HIST + t * PH + j], acc);
        sm[OFF_RED + g * 64 + j] = acc * inv;
    }
    __syncthreads();   // B6
    if (tid < 64) {
        float iv = 0.f;
#pragma unroll
        for (int g = 0; g < 8; ++g) iv += sm[OFF_RED + g * 64 + tid];
        g_inter[b * 64 + tid] = iv;
    }
}

// ============================================================
// final MLP v2: 32 rows/CTA, grid 128 (single wave),
// register-tiled 4x8 / 4x4 outer products -> FMA-bound.
// ============================================================
#define DR 32
#define F_XS   0        // 32*128 = 4096
#define F_WT   4096     // 8192
#define F_G1   12288    // 8192
#define F_MB1  20480    // 256
#define F_MB2  20736    // 128
#define F_OW   20864    // 128
#define F_TGT  20992    // 32 (int view)
#define SMEM_F_FLOATS 21056
#define SMEM_F_BYTES  (SMEM_F_FLOATS * 4)

__global__ __launch_bounds__(256) void din_final(
    const int* __restrict__ target,
    const float* __restrict__ table,
    const float* __restrict__ mw1, const float* __restrict__ mb1,
    const float* __restrict__ mw2, const float* __restrict__ mb2,
    const float* __restrict__ ow,  const float* __restrict__ ob,
    float* __restrict__ out) {
    extern __shared__ float sm[];
    int* smi = (int*)sm;
    const int tid = threadIdx.x;
    const int b0  = blockIdx.x * DR;
    const int rg  = tid >> 5;   // warp id = row group (rows rg*4..+4)
    const int cg  = tid & 31;   // lane = col group

    if (tid < DR) smi[F_TGT + tid] = target[b0 + tid];
    sm[F_MB1 + tid] = mb1[tid];
    if (tid < 128) { sm[F_MB2 + tid] = mb2[tid]; sm[F_OW + tid] = ow[tid]; }
    __syncthreads();

    // X = concat(item, interest), rows b0..b0+31
    for (int idx = tid; idx < DR * 128; idx += 256) {
        int rr = idx >> 7, c = idx & 127;
        sm[F_XS + idx] = (c < 64)
            ? table[(size_t)smi[F_TGT + rr] * 64 + c]
            : g_inter[(size_t)(b0 + rr) * 64 + (c - 64)];
    }

    // ---- stage 1: G1[32,256] = relu(X @ mw1 + mb1) ----
    // thread covers rows rg*4..+4, cols {cg*4..+4} and {128+cg*4..+4}
    float acc[32];
#pragma unroll
    for (int c = 0; c < 4; ++c) {
        float bA = sm[F_MB1 + cg * 4 + c];
        float bB = sm[F_MB1 + 128 + cg * 4 + c];
#pragma unroll
        for (int i = 0; i < 4; ++i) { acc[i * 8 + c] = bA; acc[i * 8 + 4 + c] = bB; }
    }
    for (int kt = 0; kt < 4; ++kt) {
        __syncthreads();   // XS ready (kt=0) / prior WT reads done
        {
            const float4* src = (const float4*)(mw1 + kt * 32 * 256);
            float4* dst = (float4*)(sm + F_WT);
            for (int idx = tid; idx < 2048; idx += 256) dst[idx] = src[idx];
        }
        __syncthreads();
#pragma unroll 4
        for (int k = 0; k < 32; ++k) {
            float x0 = sm[F_XS + (rg * 4 + 0) * 128 + kt * 32 + k];
            float x1 = sm[F_XS + (rg * 4 + 1) * 128 + kt * 32 + k];
            float x2 = sm[F_XS + (rg * 4 + 2) * 128 + kt * 32 + k];
            float x3 = sm[F_XS + (rg * 4 + 3) * 128 + kt * 32 + k];
            float4 wa = *(const float4*)(sm + F_WT + k * 256 + cg * 4);
            float4 wb = *(const float4*)(sm + F_WT + k * 256 + 128 + cg * 4);
            acc[0]  = fmaf(x0, wa.x, acc[0]);  acc[1]  = fmaf(x0, wa.y, acc[1]);
            acc[2]  = fmaf(x0, wa.z, acc[2]);  acc[3]  = fmaf(x0, wa.w, acc[3]);
            acc[4]  = fmaf(x0, wb.x, acc[4]);  acc[5]  = fmaf(x0, wb.y, acc[5]);
            acc[6]  = fmaf(x0, wb.z, acc[6]);  acc[7]  = fmaf(x0, wb.w, acc[7]);
            acc[8]  = fmaf(x1, wa.x, acc[8]);  acc[9]  = fmaf(x1, wa.y, acc[9]);
            acc[10] = fmaf(x1, wa.z, acc[10]); acc[11] = fmaf(x1, wa.w, acc[11]);
            acc[12] = fmaf(x1, wb.x, acc[12]); acc[13] = fmaf(x1, wb.y, acc[13]);
            acc[14] = fmaf(x1, wb.z, acc[14]); acc[15] = fmaf(x1, wb.w, acc[15]);
            acc[16] = fmaf(x2, wa.x, acc[16]); acc[17] = fmaf(x2, wa.y, acc[17]);
            acc[18] = fmaf(x2, wa.z, acc[18]); acc[19] = fmaf(x2, wa.w, acc[19]);
            acc[20] = fmaf(x2, wb.x, acc[20]); acc[21] = fmaf(x2, wb.y, acc[21]);
            acc[22] = fmaf(x2, wb.z, acc[22]); acc[23] = fmaf(x2, wb.w, acc[23]);
            acc[24] = fmaf(x3, wa.x, acc[24]); acc[25] = fmaf(x3, wa.y, acc[25]);
            acc[26] = fmaf(x3, wa.z, acc[26]); acc[27] = fmaf(x3, wa.w, acc[27]);
            acc[28] = fmaf(x3, wb.x, acc[28]); acc[29] = fmaf(x3, wb.y, acc[29]);
            acc[30] = fmaf(x3, wb.z, acc[30]); acc[31] = fmaf(x3, wb.w, acc[31]);
        }
    }
    __syncthreads();
#pragma unroll
    for (int i = 0; i < 4; ++i) {
        float4 ra = make_float4(fmaxf(acc[i*8+0],0.f), fmaxf(acc[i*8+1],0.f),
                                fmaxf(acc[i*8+2],0.f), fmaxf(acc[i*8+3],0.f));
        float4 rb = make_float4(fmaxf(acc[i*8+4],0.f), fmaxf(acc[i*8+5],0.f),
                                fmaxf(acc[i*8+6],0.f), fmaxf(acc[i*8+7],0.f));
        *(float4*)(sm + F_G1 + (rg * 4 + i) * 256 + cg * 4)       = ra;
        *(float4*)(sm + F_G1 + (rg * 4 + i) * 256 + 128 + cg * 4) = rb;
    }

    // ---- stage 2: G2[32,128] = relu(G1 @ mw2 + mb2) ----
    // thread covers rows rg*4..+4, cols cg*4..+4
    float a2[16];
#pragma unroll
    for (int c = 0; c < 4; ++c) {
        float bv = sm[F_MB2 + cg * 4 + c];
#pragma unroll
        for (int i = 0; i < 4; ++i) a2[i * 4 + c] = bv;
    }
    for (int kt = 0; kt < 8; ++kt) {
        __syncthreads();   // G1 ready (kt=0) / prior WT reads done
        {
            const float4* src = (const float4*)(mw2 + kt * 32 * 128);
            float4* dst = (float4*)(sm + F_WT);
            for (int idx = tid; idx < 1024; idx += 256) dst[idx] = src[idx];
        }
        __syncthreads();
#pragma unroll 4
        for (int k = 0; k < 32; ++k) {
            float g0 = sm[F_G1 + (rg * 4 + 0) * 256 + kt * 32 + k];
            float g1 = sm[F_G1 + (rg * 4 + 1) * 256 + kt * 32 + k];
            float g2 = sm[F_G1 + (rg * 4 + 2) * 256 + kt * 32 + k];
            float g3 = sm[F_G1 + (rg * 4 + 3) * 256 + kt * 32 + k];
            float4 wv = *(const float4*)(sm + F_WT + k * 128 + cg * 4);
            a2[0]  = fmaf(g0, wv.x, a2[0]);  a2[1]  = fmaf(g0, wv.y, a2[1]);
            a2[2]  = fmaf(g0, wv.z, a2[2]);  a2[3]  = fmaf(g0, wv.w, a2[3]);
            a2[4]  = fmaf(g1, wv.x, a2[4]);  a2[5]  = fmaf(g1, wv.y, a2[5]);
            a2[6]  = fmaf(g1, wv.z, a2[6]);  a2[7]  = fmaf(g1, wv.w, a2[7]);
            a2[8]  = fmaf(g2, wv.x, a2[8]);  a2[9]  = fmaf(g2, wv.y, a2[9]);
            a2[10] = fmaf(g2, wv.z, a2[10]); a2[11] = fmaf(g2, wv.w, a2[11]);
            a2[12] = fmaf(g3, wv.x, a2[12]); a2[13] = fmaf(g3, wv.y, a2[13]);
            a2[14] = fmaf(g3, wv.z, a2[14]); a2[15] = fmaf(g3, wv.w, a2[15]);
        }
    }

    // ---- stage 3: out = relu(G2) @ ow + ob (warp reduce; lanes = cols) ----
    float w0 = sm[F_OW + cg * 4 + 0];
    float w1 = sm[F_OW + cg * 4 + 1];
    float w2 = sm[F_OW + cg * 4 + 2];
    float w3 = sm[F_OW + cg * 4 + 3];
    float ob0 = ob[0];
#pragma unroll
    for (int i = 0; i < 4; ++i) {
        float p = fmaf(fmaxf(a2[i*4+0], 0.f), w0,
                  fmaf(fmaxf(a2[i*4+1], 0.f), w1,
                  fmaf(fmaxf(a2[i*4+2], 0.f), w2,
                       fmaxf(a2[i*4+3], 0.f) * w3)));
        p += __shfl_xor_sync(0xffffffffu, p, 16);
        p += __shfl_xor_sync(0xffffffffu, p, 8);
        p += __shfl_xor_sync(0xffffffffu, p, 4);
        p += __shfl_xor_sync(0xffffffffu, p, 2);
        p += __shfl_xor_sync(0xffffffffu, p, 1);
        if (cg == 0) out[b0 + rg * 4 + i] = p + ob0;
    }
}

// ============================================================
// launch
// ============================================================
extern "C" void kernel_launch(void* const* d_in, const int* in_sizes, int n_in,
                              void* d_out, int out_size) {
    const int*   target  = (const int*)d_in[0];
    const int*   hist_id = (const int*)d_in[1];
    const int*   mask    = (const int*)d_in[2];     // bool promoted; test != 0
    const float* table   = (const float*)d_in[3];
    const float* aw1     = (const float*)d_in[4];
    const float* ab1     = (const float*)d_in[5];
    const float* aw2     = (const float*)d_in[6];
    const float* ab2     = (const float*)d_in[7];
    const float* aow     = (const float*)d_in[8];
    const float* aob     = (const float*)d_in[9];
    const float* mw1     = (const float*)d_in[10];
    const float* mb1     = (const float*)d_in[11];
    const float* mw2     = (const float*)d_in[12];
    const float* mb2     = (const float*)d_in[13];
    const float* ow      = (const float*)d_in[14];
    const float* ob      = (const float*)d_in[15];
    float* out = (float*)d_out;

    cudaFuncSetAttribute(din_main, cudaFuncAttributeMaxDynamicSharedMemorySize, SMEM_B_BYTES);
    cudaFuncSetAttribute(din_final, cudaFuncAttributeMaxDynamicSharedMemorySize, SMEM_F_BYTES);

    prep_weights<<<8, 512>>>(aw1);
    din_main<<<B_, 512, SMEM_B_BYTES>>>(hist_id, mask, table, target, ab1,
                                        aw2, ab2, aow, aob);
    din_final<<<B_ / DR, 256, SMEM_F_BYTES>>>(target, table, mw1, mb1,
                                              mw2, mb2, ow, ob, out);
}

// round 6
// speedup vs baseline: 2.3240x; 1.1173x over previous
#include <cuda_runtime.h>
#include <cuda_bf16.h>
#include <math.h>

// Problem constants
#define B_  4096
#define T_  200
#define E_  64
#define A1_ 64
#define A2_ 32
#define M1_ 256
#define M2_ 128
#define GRID_MAIN 296   // 2 CTAs per SM x 148 SMs

// -------- device scratch (no allocations allowed) --------
__device__ float2 g_Whp[64 * 64];   // interleaved (Wh, Wp)
__device__ float  g_Wq[64 * 64];    // aw1[64:128] - aw1[128:192]
__device__ float  g_inter[B_ * 64]; // interest vectors

// ---- tf32 helpers ----
__device__ __forceinline__ unsigned int f2tf(float f) {
    unsigned int r;
    asm("cvt.rna.tf32.f32 %0, %1;" : "=r"(r) : "f"(f));
    return r;
}
__device__ __forceinline__ void mma_tf32(
    float& c0, float& c1, float& c2, float& c3,
    unsigned int a0, unsigned int a1, unsigned int a2, unsigned int a3,
    unsigned int b0, unsigned int b1) {
    asm("mma.sync.aligned.m16n8k8.row.col.f32.tf32.tf32.f32 "
        "{%0,%1,%2,%3},{%4,%5,%6,%7},{%8,%9},{%0,%1,%2,%3};"
        : "+f"(c0), "+f"(c1), "+f"(c2), "+f"(c3)
        : "r"(a0), "r"(a1), "r"(a2), "r"(a3), "r"(b0), "r"(b1));
}

// ============================================================
// prep: fold aw1 into (Wh,Wp) pairs + Wq
// ============================================================
__global__ void prep_weights(const float* __restrict__ aw1) {
    int idx = blockIdx.x * blockDim.x + threadIdx.x;
    if (idx >= 64 * 64) return;
    int j = idx & 63, k = idx >> 6;
    float a = aw1[k * 64 + j];
    float b = aw1[(64 + k) * 64 + j];
    float c = aw1[(128 + k) * 64 + j];
    float d = aw1[(192 + k) * 64 + j];
    g_Whp[k * 64 + j] = make_float2(a + c, d);
    g_Wq[k * 64 + j]  = b - c;
}

// ============================================================
// main kernel: PERSISTENT, 296 CTAs x 512 threads, 2 CTAs/SM.
// Each CTA loops over batch elements (stride 296).
// Fused tf32 attention MLP; invariant staging hoisted out of loop.
// ============================================================
#define PH 68
// smem layout (float offsets)
#define OFF_HIST  0        // 208*68 = 14144
#define OFF_WCU   14144    // 4352
#define OFF_W2U   18496    // 2304
#define OFF_QV    20800    // 64
#define OFF_QB    20864    // 64
#define OFF_AB2   20928    // 32
#define OFF_AOW   20960    // 32
#define OFF_SC    20992    // 208
#define OFF_MSK   21200    // 208 (int view)
#define OFF_WRED  21408    // 32
#define OFF_RED   21440    // 512
#define SMEM_B_FLOATS 21952
#define SMEM_B_BYTES  (SMEM_B_FLOATS * 4)

__global__ __launch_bounds__(512, 2) void din_main(
    const int* __restrict__ hist_id,
    const int* __restrict__ mask,        // bool promoted to 4-byte; test != 0
    const float* __restrict__ table,
    const int* __restrict__ target,
    const float* __restrict__ ab1,
    const float* __restrict__ aw2,
    const float* __restrict__ ab2,
    const float* __restrict__ aow,
    const float* __restrict__ aob) {
    extern __shared__ float sm[];
    unsigned int* smu = (unsigned int*)sm;
    int* smi = (int*)sm;
    const int tid = threadIdx.x;
    const int w   = tid >> 5;
    const int l   = tid & 31;
    const int l4  = l >> 2;   // 0..7
    const int lm  = l & 3;    // 0..3

    // ---- loop-invariant staging (once per CTA) ----
    if (tid < 32)        sm[OFF_AB2 + tid]      = ab2[tid];
    else if (tid < 64)   sm[OFF_AOW + tid - 32] = aow[tid - 32];
    for (int idx = tid; idx < 64 * 32; idx += 512) {
        int n = idx & 31, k = idx >> 5;
        smu[OFF_W2U + k * 36 + n] = f2tf(aw2[k * 32 + n]);
    }
    const float aob0 = aob[0];
    const float ab1v = (tid < 64) ? ab1[tid] : 0.f;

    for (int b = blockIdx.x; b < B_; b += GRID_MAIN) {
        __syncthreads();   // B0: prior iteration fully done / invariants ready

        // --- per-batch staging: item embedding + mask ---
        if (tid < 64)
            sm[OFF_QV + tid] = table[(size_t)target[b] * 64 + tid];
        else if (tid < 264)
            smi[OFF_MSK + tid - 64] = mask[b * T_ + tid - 64];
        __syncthreads();   // B1: QV ready

        // --- qb[n] = ab1[n] + item @ Wq (threads 0..63) ---
        if (tid < 64) {
            float acc = ab1v;
#pragma unroll 8
            for (int k = 0; k < 64; ++k)
                acc = fmaf(sm[OFF_QV + k], g_Wq[k * 64 + tid], acc);
            sm[OFF_QB + tid] = acc;
        }
        // --- fold Wc[k][n] = Wh + q[k]*Wp (float2 loads), store tf32 bits ---
        for (int idx = tid; idx < 64 * 64; idx += 512) {
            int n = idx & 63, k = idx >> 6;
            float2 hp = g_Whp[k * 64 + n];
            smu[OFF_WCU + k * PH + n] = f2tf(fmaf(sm[OFF_QV + k], hp.y, hp.x));
        }
        // --- gather history embeddings ---
        {
            const float4* tab4 = (const float4*)table;
            float4* hist4 = (float4*)(sm + OFF_HIST);
            for (int idx = tid; idx < T_ * 16; idx += 512) {
                int t = idx >> 4, v = idx & 15;
                hist4[t * 17 + v] = tab4[(size_t)hist_id[b * T_ + t] * 16 + v];
            }
            for (int idx = tid; idx < 8 * 17; idx += 512) {
                int t = 200 + idx / 17, v = idx % 17;
                hist4[t * 17 + v] = make_float4(0.f, 0.f, 0.f, 0.f);
            }
        }
        __syncthreads();   // B2: all operands staged

        // ====== fused attention MLP: warps 0..12 own rows [16w, 16w+16) ======
        if (w < 13) {
            const int mt = w;

            unsigned int au[32];
            {
                const float* abase = sm + OFF_HIST + (mt * 16 + l4) * PH + lm;
#pragma unroll
                for (int k = 0; k < 8; ++k) {
                    au[4 * k + 0] = f2tf(abase[k * 8]);
                    au[4 * k + 1] = f2tf(abase[8 * PH + k * 8]);
                    au[4 * k + 2] = f2tf(abase[k * 8 + 4]);
                    au[4 * k + 3] = f2tf(abase[8 * PH + k * 8 + 4]);
                }
            }

            float d0[4], d1[4], d2[4], d3[4];
#pragma unroll
            for (int nt2 = 0; nt2 < 4; ++nt2) {
                float bb0 = sm[OFF_AB2 + nt2 * 8 + 2 * lm];
                float bb1 = sm[OFF_AB2 + nt2 * 8 + 2 * lm + 1];
                d0[nt2] = bb0; d1[nt2] = bb1; d2[nt2] = bb0; d3[nt2] = bb1;
            }

            const unsigned int* wc_col = smu + OFF_WCU + lm * PH;
            const unsigned int* w2_col = smu + OFF_W2U + lm * 36 + l4;

            for (int kk = 0; kk < 8; ++kk) {
                float c0 = sm[OFF_QB + kk * 8 + 2 * lm];
                float c1 = sm[OFF_QB + kk * 8 + 2 * lm + 1];
                float c2 = c0, c3 = c1;
                const unsigned int* wcb = wc_col + kk * 8 + l4;
#pragma unroll
                for (int k = 0; k < 8; ++k) {
                    unsigned int b0v = wcb[k * 8 * PH];
                    unsigned int b1v = wcb[k * 8 * PH + 4 * PH];
                    mma_tf32(c0, c1, c2, c3,
                             au[4 * k], au[4 * k + 1], au[4 * k + 2], au[4 * k + 3],
                             b0v, b1v);
                }
                c0 = fmaxf(c0, 0.f); c1 = fmaxf(c1, 0.f);
                c2 = fmaxf(c2, 0.f); c3 = fmaxf(c3, 0.f);

                int src1 = (l & ~3) + (lm >> 1);
                int src2 = src1 + 2;
                float v0a = __shfl_sync(0xffffffffu, c0, src1);
                float v1a = __shfl_sync(0xffffffffu, c1, src1);
                float v2a = __shfl_sync(0xffffffffu, c2, src1);
                float v3a = __shfl_sync(0xffffffffu, c3, src1);
                float v0b = __shfl_sync(0xffffffffu, c0, src2);
                float v1b = __shfl_sync(0xffffffffu, c1, src2);
                float v2b = __shfl_sync(0xffffffffu, c2, src2);
                float v3b = __shfl_sync(0xffffffffu, c3, src2);
                bool hi = (lm & 1);
                unsigned int a0 = f2tf(hi ? v1a : v0a);
                unsigned int a1 = f2tf(hi ? v3a : v2a);
                unsigned int a2 = f2tf(hi ? v1b : v0b);
                unsigned int a3 = f2tf(hi ? v3b : v2b);

                const unsigned int* w2b = w2_col + kk * 8 * 36;
#pragma unroll
                for (int nt2 = 0; nt2 < 4; ++nt2) {
                    unsigned int b0v = w2b[nt2 * 8];
                    unsigned int b1v = w2b[nt2 * 8 + 4 * 36];
                    mma_tf32(d0[nt2], d1[nt2], d2[nt2], d3[nt2],
                             a0, a1, a2, a3, b0v, b1v);
                }
            }

            float p01 = 0.f, p23 = 0.f;
#pragma unroll
            for (int nt2 = 0; nt2 < 4; ++nt2) {
                float w0 = sm[OFF_AOW + nt2 * 8 + 2 * lm];
                float w1 = sm[OFF_AOW + nt2 * 8 + 2 * lm + 1];
                p01 = fmaf(fmaxf(d0[nt2], 0.f), w0, fmaf(fmaxf(d1[nt2], 0.f), w1, p01));
                p23 = fmaf(fmaxf(d2[nt2], 0.f), w0, fmaf(fmaxf(d3[nt2], 0.f), w1, p23));
            }
            p01 += __shfl_xor_sync(0xffffffffu, p01, 1);
            p01 += __shfl_xor_sync(0xffffffffu, p01, 2);
            p23 += __shfl_xor_sync(0xffffffffu, p23, 1);
            p23 += __shfl_xor_sync(0xffffffffu, p23, 2);
            if (lm == 0) {
                int r0 = mt * 16 + l4;
                int r1 = r0 + 8;
                if (r0 < T_)
                    sm[OFF_SC + r0] = (smi[OFF_MSK + r0] != 0) ? p01 + aob0 : -1e9f;
                if (r1 < T_)
                    sm[OFF_SC + r1] = (smi[OFF_MSK + r1] != 0) ? p23 + aob0 : -1e9f;
            }
        }
        __syncthreads();   // B3: scores ready

        // ---- softmax ----
        float v = (tid < T_) ? sm[OFF_SC + tid] : -1e30f;
        float m = v;
        m = fmaxf(m, __shfl_xor_sync(0xffffffffu, m, 16));
        m = fmaxf(m, __shfl_xor_sync(0xffffffffu, m, 8));
        m = fmaxf(m, __shfl_xor_sync(0xffffffffu, m, 4));
        m = fmaxf(m, __shfl_xor_sync(0xffffffffu, m, 2));
        m = fmaxf(m, __shfl_xor_sync(0xffffffffu, m, 1));
        if (l == 0) sm[OFF_WRED + w] = m;
        __syncthreads();   // B4
        float gm = sm[OFF_WRED + 0];
#pragma unroll
        for (int i = 1; i < 16; ++i) gm = fmaxf(gm, sm[OFF_WRED + i]);
        float e = (tid < T_) ? __expf(v - gm) : 0.f;
        if (tid < T_) sm[OFF_SC + tid] = e;
        float s = e;
        s += __shfl_xor_sync(0xffffffffu, s, 16);
        s += __shfl_xor_sync(0xffffffffu, s, 8);
        s += __shfl_xor_sync(0xffffffffu, s, 4);
        s += __shfl_xor_sync(0xffffffffu, s, 2);
        s += __shfl_xor_sync(0xffffffffu, s, 1);
        if (l == 0) sm[OFF_WRED + 16 + w] = s;
        __syncthreads();   // B5

        // ---- interest (normalization folded in) ----
        {
            float ss = sm[OFF_WRED + 16];
#pragma unroll
            for (int i = 1; i < 16; ++i) ss += sm[OFF_WRED + 16 + i];
            float inv = 1.f / ss;
            int j = tid & 63, g = tid >> 6;
            float acc = 0.f;
            for (int t = g * 25; t < (g + 1) * 25; ++t)
                acc = fmaf(sm[OFF_SC + t], sm[OFF_HIST + t * PH + j], acc);
            sm[OFF_RED + g * 64 + j] = acc * inv;
        }
        __syncthreads();   // B6
        if (tid < 64) {
            float iv = 0.f;
#pragma unroll
            for (int g = 0; g < 8; ++g) iv += sm[OFF_RED + g * 64 + tid];
            g_inter[b * 64 + tid] = iv;
        }
        // next iteration starts with B0 barrier protecting all regions
    }
}

// ============================================================
// final MLP: 32 rows/CTA, grid 128, register-tiled outer products.
// ============================================================
#define DR 32
#define F_XS   0        // 32*128 = 4096
#define F_WT   4096     // 8192
#define F_G1   12288    // 8192
#define F_MB1  20480    // 256
#define F_MB2  20736    // 128
#define F_OW   20864    // 128
#define F_TGT  20992    // 32 (int view)
#define SMEM_F_FLOATS 21056
#define SMEM_F_BYTES  (SMEM_F_FLOATS * 4)

__global__ __launch_bounds__(256) void din_final(
    const int* __restrict__ target,
    const float* __restrict__ table,
    const float* __restrict__ mw1, const float* __restrict__ mb1,
    const float* __restrict__ mw2, const float* __restrict__ mb2,
    const float* __restrict__ ow,  const float* __restrict__ ob,
    float* __restrict__ out) {
    extern __shared__ float sm[];
    int* smi = (int*)sm;
    const int tid = threadIdx.x;
    const int b0  = blockIdx.x * DR;
    const int rg  = tid >> 5;
    const int cg  = tid & 31;

    if (tid < DR) smi[F_TGT + tid] = target[b0 + tid];
    sm[F_MB1 + tid] = mb1[tid];
    if (tid < 128) { sm[F_MB2 + tid] = mb2[tid]; sm[F_OW + tid] = ow[tid]; }
    __syncthreads();

    for (int idx = tid; idx < DR * 128; idx += 256) {
        int rr = idx >> 7, c = idx & 127;
        sm[F_XS + idx] = (c < 64)
            ? table[(size_t)smi[F_TGT + rr] * 64 + c]
            : g_inter[(size_t)(b0 + rr) * 64 + (c - 64)];
    }

    float acc[32];
#pragma unroll
    for (int c = 0; c < 4; ++c) {
        float bA = sm[F_MB1 + cg * 4 + c];
        float bB = sm[F_MB1 + 128 + cg * 4 + c];
#pragma unroll
        for (int i = 0; i < 4; ++i) { acc[i * 8 + c] = bA; acc[i * 8 + 4 + c] = bB; }
    }
    for (int kt = 0; kt < 4; ++kt) {
        __syncthreads();
        {
            const float4* src = (const float4*)(mw1 + kt * 32 * 256);
            float4* dst = (float4*)(sm + F_WT);
            for (int idx = tid; idx < 2048; idx += 256) dst[idx] = src[idx];
        }
        __syncthreads();
#pragma unroll 4
        for (int k = 0; k < 32; ++k) {
            float x0 = sm[F_XS + (rg * 4 + 0) * 128 + kt * 32 + k];
            float x1 = sm[F_XS + (rg * 4 + 1) * 128 + kt * 32 + k];
            float x2 = sm[F_XS + (rg * 4 + 2) * 128 + kt * 32 + k];
            float x3 = sm[F_XS + (rg * 4 + 3) * 128 + kt * 32 + k];
            float4 wa = *(const float4*)(sm + F_WT + k * 256 + cg * 4);
            float4 wb = *(const float4*)(sm + F_WT + k * 256 + 128 + cg * 4);
            acc[0]  = fmaf(x0, wa.x, acc[0]);  acc[1]  = fmaf(x0, wa.y, acc[1]);
            acc[2]  = fmaf(x0, wa.z, acc[2]);  acc[3]  = fmaf(x0, wa.w, acc[3]);
            acc[4]  = fmaf(x0, wb.x, acc[4]);  acc[5]  = fmaf(x0, wb.y, acc[5]);
            acc[6]  = fmaf(x0, wb.z, acc[6]);  acc[7]  = fmaf(x0, wb.w, acc[7]);
            acc[8]  = fmaf(x1, wa.x, acc[8]);  acc[9]  = fmaf(x1, wa.y, acc[9]);
            acc[10] = fmaf(x1, wa.z, acc[10]); acc[11] = fmaf(x1, wa.w, acc[11]);
            acc[12] = fmaf(x1, wb.x, acc[12]); acc[13] = fmaf(x1, wb.y, acc[13]);
            acc[14] = fmaf(x1, wb.z, acc[14]); acc[15] = fmaf(x1, wb.w, acc[15]);
            acc[16] = fmaf(x2, wa.x, acc[16]); acc[17] = fmaf(x2, wa.y, acc[17]);
            acc[18] = fmaf(x2, wa.z, acc[18]); acc[19] = fmaf(x2, wa.w, acc[19]);
            acc[20] = fmaf(x2, wb.x, acc[20]); acc[21] = fmaf(x2, wb.y, acc[21]);
            acc[22] = fmaf(x2, wb.z, acc[22]); acc[23] = fmaf(x2, wb.w, acc[23]);
            acc[24] = fmaf(x3, wa.x, acc[24]); acc[25] = fmaf(x3, wa.y, acc[25]);
            acc[26] = fmaf(x3, wa.z, acc[26]); acc[27] = fmaf(x3, wa.w, acc[27]);
            acc[28] = fmaf(x3, wb.x, acc[28]); acc[29] = fmaf(x3, wb.y, acc[29]);
            acc[30] = fmaf(x3, wb.z, acc[30]); acc[31] = fmaf(x3, wb.w, acc[31]);
        }
    }
    __syncthreads();
#pragma unroll
    for (int i = 0; i < 4; ++i) {
        float4 ra = make_float4(fmaxf(acc[i*8+0],0.f), fmaxf(acc[i*8+1],0.f),
                                fmaxf(acc[i*8+2],0.f), fmaxf(acc[i*8+3],0.f));
        float4 rb = make_float4(fmaxf(acc[i*8+4],0.f), fmaxf(acc[i*8+5],0.f),
                                fmaxf(acc[i*8+6],0.f), fmaxf(acc[i*8+7],0.f));
        *(float4*)(sm + F_G1 + (rg * 4 + i) * 256 + cg * 4)       = ra;
        *(float4*)(sm + F_G1 + (rg * 4 + i) * 256 + 128 + cg * 4) = rb;
    }

    float a2[16];
#pragma unroll
    for (int c = 0; c < 4; ++c) {
        float bv = sm[F_MB2 + cg * 4 + c];
#pragma unroll
        for (int i = 0; i < 4; ++i) a2[i * 4 + c] = bv;
    }
    for (int kt = 0; kt < 8; ++kt) {
        __syncthreads();
        {
            const float4* src = (const float4*)(mw2 + kt * 32 * 128);
            float4* dst = (float4*)(sm + F_WT);
            for (int idx = tid; idx < 1024; idx += 256) dst[idx] = src[idx];
        }
        __syncthreads();
#pragma unroll 4
        for (int k = 0; k < 32; ++k) {
            float g0 = sm[F_G1 + (rg * 4 + 0) * 256 + kt * 32 + k];
            float g1 = sm[F_G1 + (rg * 4 + 1) * 256 + kt * 32 + k];
            float g2 = sm[F_G1 + (rg * 4 + 2) * 256 + kt * 32 + k];
            float g3 = sm[F_G1 + (rg * 4 + 3) * 256 + kt * 32 + k];
            float4 wv = *(const float4*)(sm + F_WT + k * 128 + cg * 4);
            a2[0]  = fmaf(g0, wv.x, a2[0]);  a2[1]  = fmaf(g0, wv.y, a2[1]);
            a2[2]  = fmaf(g0, wv.z, a2[2]);  a2[3]  = fmaf(g0, wv.w, a2[3]);
            a2[4]  = fmaf(g1, wv.x, a2[4]);  a2[5]  = fmaf(g1, wv.y, a2[5]);
            a2[6]  = fmaf(g1, wv.z, a2[6]);  a2[7]  = fmaf(g1, wv.w, a2[7]);
            a2[8]  = fmaf(g2, wv.x, a2[8]);  a2[9]  = fmaf(g2, wv.y, a2[9]);
            a2[10] = fmaf(g2, wv.z, a2[10]); a2[11] = fmaf(g2, wv.w, a2[11]);
            a2[12] = fmaf(g3, wv.x, a2[12]); a2[13] = fmaf(g3, wv.y, a2[13]);
            a2[14] = fmaf(g3, wv.z, a2[14]); a2[15] = fmaf(g3, wv.w, a2[15]);
        }
    }

    float w0 = sm[F_OW + cg * 4 + 0];
    float w1 = sm[F_OW + cg * 4 + 1];
    float w2 = sm[F_OW + cg * 4 + 2];
    float w3 = sm[F_OW + cg * 4 + 3];
    float ob0 = ob[0];
#pragma unroll
    for (int i = 0; i < 4; ++i) {
        float p = fmaf(fmaxf(a2[i*4+0], 0.f), w0,
                  fmaf(fmaxf(a2[i*4+1], 0.f), w1,
                  fmaf(fmaxf(a2[i*4+2], 0.f), w2,
                       fmaxf(a2[i*4+3], 0.f) * w3)));
        p += __shfl_xor_sync(0xffffffffu, p, 16);
        p += __shfl_xor_sync(0xffffffffu, p, 8);
        p += __shfl_xor_sync(0xffffffffu, p, 4);
        p += __shfl_xor_sync(0xffffffffu, p, 2);
        p += __shfl_xor_sync(0xffffffffu, p, 1);
        if (cg == 0) out[b0 + rg * 4 + i] = p + ob0;
    }
}

// ============================================================
// launch
// ============================================================
extern "C" void kernel_launch(void* const* d_in, const int* in_sizes, int n_in,
                              void* d_out, int out_size) {
    const int*   target  = (const int*)d_in[0];
    const int*   hist_id = (const int*)d_in[1];
    const int*   mask    = (const int*)d_in[2];     // bool promoted; test != 0
    const float* table   = (const float*)d_in[3];
    const float* aw1     = (const float*)d_in[4];
    const float* ab1     = (const float*)d_in[5];
    const float* aw2     = (const float*)d_in[6];
    const float* ab2     = (const float*)d_in[7];
    const float* aow     = (const float*)d_in[8];
    const float* aob     = (const float*)d_in[9];
    const float* mw1     = (const float*)d_in[10];
    const float* mb1     = (const float*)d_in[11];
    const float* mw2     = (const float*)d_in[12];
    const float* mb2     = (const float*)d_in[13];
    const float* ow      = (const float*)d_in[14];
    const float* ob      = (const float*)d_in[15];
    float* out = (float*)d_out;

    cudaFuncSetAttribute(din_main, cudaFuncAttributeMaxDynamicSharedMemorySize, SMEM_B_BYTES);
    cudaFuncSetAttribute(din_final, cudaFuncAttributeMaxDynamicSharedMemorySize, SMEM_F_BYTES);

    prep_weights<<<8, 512>>>(aw1);
    din_main<<<GRID_MAIN, 512, SMEM_B_BYTES>>>(hist_id, mask, table, target, ab1,
                                               aw2, ab2, aow, aob);
    din_final<<<B_ / DR, 256, SMEM_F_BYTES>>>(target, table, mw1, mb1,
                                              mw2, mb2, ow, ob, out);
}

// round 7
// speedup vs baseline: 2.5657x; 1.1040x over previous
#include <cuda_runtime.h>
#include <cuda_bf16.h>
#include <math.h>

// Problem constants
#define B_  4096
#define T_  200
#define E_  64
#define A1_ 64
#define A2_ 32
#define M1_ 256
#define M2_ 128
#define GRID_MAIN 296   // 2 CTAs per SM x 148 SMs

// -------- device scratch (no allocations allowed) --------
__device__ float2 g_Whp[64 * 64];   // interleaved (Wh, Wp)
__device__ float  g_Wq[64 * 64];    // aw1[64:128] - aw1[128:192]
__device__ float  g_inter[B_ * 64]; // interest vectors

// ---- tf32 helpers ----
__device__ __forceinline__ unsigned int f2tf(float f) {
    unsigned int r;
    asm("cvt.rna.tf32.f32 %0, %1;" : "=r"(r) : "f"(f));
    return r;
}
__device__ __forceinline__ void mma_tf32(
    float& c0, float& c1, float& c2, float& c3,
    unsigned int a0, unsigned int a1, unsigned int a2, unsigned int a3,
    unsigned int b0, unsigned int b1) {
    asm("mma.sync.aligned.m16n8k8.row.col.f32.tf32.tf32.f32 "
        "{%0,%1,%2,%3},{%4,%5,%6,%7},{%8,%9},{%0,%1,%2,%3};"
        : "+f"(c0), "+f"(c1), "+f"(c2), "+f"(c3)
        : "r"(a0), "r"(a1), "r"(a2), "r"(a3), "r"(b0), "r"(b1));
}

// ============================================================
// prep: fold aw1 into (Wh,Wp) pairs + Wq
// ============================================================
__global__ void prep_weights(const float* __restrict__ aw1) {
    int idx = blockIdx.x * blockDim.x + threadIdx.x;
    if (idx >= 64 * 64) return;
    int j = idx & 63, k = idx >> 6;
    float a = aw1[k * 64 + j];
    float b = aw1[(64 + k) * 64 + j];
    float c = aw1[(128 + k) * 64 + j];
    float d = aw1[(192 + k) * 64 + j];
    g_Whp[k * 64 + j] = make_float2(a + c, d);
    g_Wq[k * 64 + j]  = b - c;
}

// ============================================================
// main kernel: PERSISTENT, 296 CTAs x 512 threads, 2 CTAs/SM.
// Whp staged in smem as bf16 pairs (fold = LDS only); qb parallel.
// ============================================================
#define PH 68
// smem layout (float offsets)
#define OFF_HIST  0        // 208*68 = 14144
#define OFF_WCU   14144    // 4352
#define OFF_W2U   18496    // 2304
#define OFF_QV    20800    // 64
#define OFF_QB    20864    // 64
#define OFF_AB2   20928    // 32
#define OFF_AOW   20960    // 32
#define OFF_SC    20992    // 208
#define OFF_MSK   21200    // 208 (int view)
#define OFF_WRED  21408    // 32
#define OFF_RED   21440    // 512
#define OFF_WHPB  21952    // 4096 (bf16x2 packed Wh,Wp)
#define SMEM_B_FLOATS 26048
#define SMEM_B_BYTES  (SMEM_B_FLOATS * 4)

__global__ __launch_bounds__(512, 2) void din_main(
    const int* __restrict__ hist_id,
    const int* __restrict__ mask,        // bool promoted to 4-byte; test != 0
    const float* __restrict__ table,
    const int* __restrict__ target,
    const float* __restrict__ ab1,
    const float* __restrict__ aw2,
    const float* __restrict__ ab2,
    const float* __restrict__ aow,
    const float* __restrict__ aob) {
    extern __shared__ float sm[];
    unsigned int* smu = (unsigned int*)sm;
    int* smi = (int*)sm;
    __nv_bfloat162* whpb = (__nv_bfloat162*)(smu + OFF_WHPB);
    const int tid = threadIdx.x;
    const int w   = tid >> 5;
    const int l   = tid & 31;
    const int l4  = l >> 2;   // 0..7
    const int lm  = l & 3;    // 0..3

    // ---- loop-invariant staging (once per CTA) ----
    if (tid < 32)        sm[OFF_AB2 + tid]      = ab2[tid];
    else if (tid < 64)   sm[OFF_AOW + tid - 32] = aow[tid - 32];
    for (int idx = tid; idx < 64 * 32; idx += 512) {
        int n = idx & 31, k = idx >> 5;
        smu[OFF_W2U + k * 36 + n] = f2tf(aw2[k * 32 + n]);
    }
    for (int idx = tid; idx < 64 * 64; idx += 512) {
        float2 hp = g_Whp[idx];
        __nv_bfloat162 v;
        v.x = __float2bfloat16(hp.x);   // Wh
        v.y = __float2bfloat16(hp.y);   // Wp
        whpb[idx] = v;
    }
    const float aob0 = aob[0];
    const float ab1v = (tid < 64) ? ab1[tid] : 0.f;

    for (int b = blockIdx.x; b < B_; b += GRID_MAIN) {
        __syncthreads();   // B0: prior iteration done / invariants ready

        // --- per-batch staging: item embedding + mask ---
        if (tid < 64)
            sm[OFF_QV + tid] = table[(size_t)target[b] * 64 + tid];
        else if (tid < 264)
            smi[OFF_MSK + tid - 64] = mask[b * T_ + tid - 64];
        __syncthreads();   // B1: QV ready

        // --- qb partials: all 512 threads (n = tid&63, kchunk = tid>>6) ---
        {
            int n = tid & 63, kc = tid >> 6;
            float acc = 0.f;
#pragma unroll
            for (int i = 0; i < 8; ++i)
                acc = fmaf(sm[OFF_QV + kc * 8 + i], g_Wq[(kc * 8 + i) * 64 + n], acc);
            sm[OFF_RED + kc * 64 + n] = acc;
        }
        __syncthreads();   // B1.5: partials ready
        if (tid < 64) {
            float acc = ab1v;
#pragma unroll
            for (int kc = 0; kc < 8; ++kc) acc += sm[OFF_RED + kc * 64 + tid];
            sm[OFF_QB + tid] = acc;
        }
        // --- fold Wc[k][n] = Wh + q[k]*Wp (LDS bf16 pairs), store tf32 bits ---
        for (int idx = tid; idx < 64 * 64; idx += 512) {
            int n = idx & 63, k = idx >> 6;
            __nv_bfloat162 hp = whpb[idx];
            smu[OFF_WCU + k * PH + n] =
                f2tf(fmaf(sm[OFF_QV + k], __bfloat162float(hp.y),
                          __bfloat162float(hp.x)));
        }
        // --- gather history embeddings ---
        {
            const float4* tab4 = (const float4*)table;
            float4* hist4 = (float4*)(sm + OFF_HIST);
            for (int idx = tid; idx < T_ * 16; idx += 512) {
                int t = idx >> 4, v = idx & 15;
                hist4[t * 17 + v] = tab4[(size_t)hist_id[b * T_ + t] * 16 + v];
            }
            for (int idx = tid; idx < 8 * 17; idx += 512) {
                int t = 200 + idx / 17, v = idx % 17;
                hist4[t * 17 + v] = make_float4(0.f, 0.f, 0.f, 0.f);
            }
        }
        __syncthreads();   // B2: all operands staged

        // ====== fused attention MLP: warps 0..12 own rows [16w, 16w+16) ======
        if (w < 13) {
            const int mt = w;

            unsigned int au[32];
            {
                const float* abase = sm + OFF_HIST + (mt * 16 + l4) * PH + lm;
#pragma unroll
                for (int k = 0; k < 8; ++k) {
                    au[4 * k + 0] = f2tf(abase[k * 8]);
                    au[4 * k + 1] = f2tf(abase[8 * PH + k * 8]);
                    au[4 * k + 2] = f2tf(abase[k * 8 + 4]);
                    au[4 * k + 3] = f2tf(abase[8 * PH + k * 8 + 4]);
                }
            }

            float d0[4], d1[4], d2[4], d3[4];
#pragma unroll
            for (int nt2 = 0; nt2 < 4; ++nt2) {
                float bb0 = sm[OFF_AB2 + nt2 * 8 + 2 * lm];
                float bb1 = sm[OFF_AB2 + nt2 * 8 + 2 * lm + 1];
                d0[nt2] = bb0; d1[nt2] = bb1; d2[nt2] = bb0; d3[nt2] = bb1;
            }

            const unsigned int* wc_col = smu + OFF_WCU + lm * PH;
            const unsigned int* w2_col = smu + OFF_W2U + lm * 36 + l4;

            for (int kk = 0; kk < 8; ++kk) {
                float c0 = sm[OFF_QB + kk * 8 + 2 * lm];
                float c1 = sm[OFF_QB + kk * 8 + 2 * lm + 1];
                float c2 = c0, c3 = c1;
                const unsigned int* wcb = wc_col + kk * 8 + l4;
#pragma unroll
                for (int k = 0; k < 8; ++k) {
                    unsigned int b0v = wcb[k * 8 * PH];
                    unsigned int b1v = wcb[k * 8 * PH + 4 * PH];
                    mma_tf32(c0, c1, c2, c3,
                             au[4 * k], au[4 * k + 1], au[4 * k + 2], au[4 * k + 3],
                             b0v, b1v);
                }
                c0 = fmaxf(c0, 0.f); c1 = fmaxf(c1, 0.f);
                c2 = fmaxf(c2, 0.f); c3 = fmaxf(c3, 0.f);

                int src1 = (l & ~3) + (lm >> 1);
                int src2 = src1 + 2;
                float v0a = __shfl_sync(0xffffffffu, c0, src1);
                float v1a = __shfl_sync(0xffffffffu, c1, src1);
                float v2a = __shfl_sync(0xffffffffu, c2, src1);
                float v3a = __shfl_sync(0xffffffffu, c3, src1);
                float v0b = __shfl_sync(0xffffffffu, c0, src2);
                float v1b = __shfl_sync(0xffffffffu, c1, src2);
                float v2b = __shfl_sync(0xffffffffu, c2, src2);
                float v3b = __shfl_sync(0xffffffffu, c3, src2);
                bool hi = (lm & 1);
                unsigned int a0 = f2tf(hi ? v1a : v0a);
                unsigned int a1 = f2tf(hi ? v3a : v2a);
                unsigned int a2 = f2tf(hi ? v1b : v0b);
                unsigned int a3 = f2tf(hi ? v3b : v2b);

                const unsigned int* w2b = w2_col + kk * 8 * 36;
#pragma unroll
                for (int nt2 = 0; nt2 < 4; ++nt2) {
                    unsigned int b0v = w2b[nt2 * 8];
                    unsigned int b1v = w2b[nt2 * 8 + 4 * 36];
                    mma_tf32(d0[nt2], d1[nt2], d2[nt2], d3[nt2],
                             a0, a1, a2, a3, b0v, b1v);
                }
            }

            float p01 = 0.f, p23 = 0.f;
#pragma unroll
            for (int nt2 = 0; nt2 < 4; ++nt2) {
                float w0 = sm[OFF_AOW + nt2 * 8 + 2 * lm];
                float w1 = sm[OFF_AOW + nt2 * 8 + 2 * lm + 1];
                p01 = fmaf(fmaxf(d0[nt2], 0.f), w0, fmaf(fmaxf(d1[nt2], 0.f), w1, p01));
                p23 = fmaf(fmaxf(d2[nt2], 0.f), w0, fmaf(fmaxf(d3[nt2], 0.f), w1, p23));
            }
            p01 += __shfl_xor_sync(0xffffffffu, p01, 1);
            p01 += __shfl_xor_sync(0xffffffffu, p01, 2);
            p23 += __shfl_xor_sync(0xffffffffu, p23, 1);
            p23 += __shfl_xor_sync(0xffffffffu, p23, 2);
            if (lm == 0) {
                int r0 = mt * 16 + l4;
                int r1 = r0 + 8;
                if (r0 < T_)
                    sm[OFF_SC + r0] = (smi[OFF_MSK + r0] != 0) ? p01 + aob0 : -1e9f;
                if (r1 < T_)
                    sm[OFF_SC + r1] = (smi[OFF_MSK + r1] != 0) ? p23 + aob0 : -1e9f;
            }
        }
        __syncthreads();   // B3: scores ready

        // ---- softmax ----
        float v = (tid < T_) ? sm[OFF_SC + tid] : -1e30f;
        float m = v;
        m = fmaxf(m, __shfl_xor_sync(0xffffffffu, m, 16));
        m = fmaxf(m, __shfl_xor_sync(0xffffffffu, m, 8));
        m = fmaxf(m, __shfl_xor_sync(0xffffffffu, m, 4));
        m = fmaxf(m, __shfl_xor_sync(0xffffffffu, m, 2));
        m = fmaxf(m, __shfl_xor_sync(0xffffffffu, m, 1));
        if (l == 0) sm[OFF_WRED + w] = m;
        __syncthreads();   // B4
        float gm = sm[OFF_WRED + 0];
#pragma unroll
        for (int i = 1; i < 16; ++i) gm = fmaxf(gm, sm[OFF_WRED + i]);
        float e = (tid < T_) ? __expf(v - gm) : 0.f;
        if (tid < T_) sm[OFF_SC + tid] = e;
        float s = e;
        s += __shfl_xor_sync(0xffffffffu, s, 16);
        s += __shfl_xor_sync(0xffffffffu, s, 8);
        s += __shfl_xor_sync(0xffffffffu, s, 4);
        s += __shfl_xor_sync(0xffffffffu, s, 2);
        s += __shfl_xor_sync(0xffffffffu, s, 1);
        if (l == 0) sm[OFF_WRED + 16 + w] = s;
        __syncthreads();   // B5

        // ---- interest (normalization folded in) ----
        {
            float ss = sm[OFF_WRED + 16];
#pragma unroll
            for (int i = 1; i < 16; ++i) ss += sm[OFF_WRED + 16 + i];
            float inv = 1.f / ss;
            int j = tid & 63, g = tid >> 6;
            float acc = 0.f;
            for (int t = g * 25; t < (g + 1) * 25; ++t)
                acc = fmaf(sm[OFF_SC + t], sm[OFF_HIST + t * PH + j], acc);
            sm[OFF_RED + g * 64 + j] = acc * inv;
        }
        __syncthreads();   // B6
        if (tid < 64) {
            float iv = 0.f;
#pragma unroll
            for (int g = 0; g < 8; ++g) iv += sm[OFF_RED + g * 64 + tid];
            g_inter[b * 64 + tid] = iv;
        }
    }
}

// ============================================================
// final MLP v3: tf32 tensor cores. 256 threads, 32 rows/CTA, grid 128.
// stage1: X[32,128]@mw1[128,256]; stage2: G1@mw2[256,128]; stage3 dot.
// ============================================================
#define DR  32
#define FPX 136   // X / mw2-chunk pitch (8l4+lm banks distinct)
#define FPW 264   // mw1-chunk / G1 pitch (8lm+l4 banks distinct)
#define FX    0        // 32*136 = 4352 (tf32 bits)
#define FG1   4352     // 32*264 = 8448 -> 12800 (tf32 bits)
#define FWT   12800    // 32*264 = 8448 -> 21248 (tf32 bits)
#define FMB1  21248    // 256
#define FMB2  21504    // 128
#define FOW   21632    // 128
#define FRED  21760    // 256
#define FTGT  22016    // 32 (int view)
#define SMEM_F_FLOATS 22048
#define SMEM_F_BYTES  (SMEM_F_FLOATS * 4)

__global__ __launch_bounds__(256) void din_final(
    const int* __restrict__ target,
    const float* __restrict__ table,
    const float* __restrict__ mw1, const float* __restrict__ mb1,
    const float* __restrict__ mw2, const float* __restrict__ mb2,
    const float* __restrict__ ow,  const float* __restrict__ ob,
    float* __restrict__ out) {
    extern __shared__ float sm[];
    unsigned int* smu = (unsigned int*)sm;
    int* smi = (int*)sm;
    const int tid = threadIdx.x;
    const int w   = tid >> 5;   // 0..7
    const int l   = tid & 31;
    const int l4  = l >> 2;
    const int lm  = l & 3;
    const int b0  = blockIdx.x * DR;

    if (tid < DR) smi[FTGT + tid] = target[b0 + tid];
    sm[FMB1 + tid] = mb1[tid];
    if (tid < 128) { sm[FMB2 + tid] = mb2[tid]; sm[FOW + tid] = ow[tid]; }
    __syncthreads();

    // ---- X = concat(item, interest) as tf32 bits ----
    {
        const float4* tab4 = (const float4*)table;
        const float4* int4p = (const float4*)g_inter;
        for (int idx = tid; idx < DR * 32; idx += 256) {
            int rr = idx >> 5, v = idx & 31;
            float4 x = (v < 16)
                ? tab4[(size_t)smi[FTGT + rr] * 16 + v]
                : int4p[(size_t)(b0 + rr) * 16 + (v - 16)];
            uint4 u = make_uint4(f2tf(x.x), f2tf(x.y), f2tf(x.z), f2tf(x.w));
            *(uint4*)(smu + FX + rr * FPX + v * 4) = u;
        }
    }

    // ---- stage 1: acc1 = X @ mw1 + mb1 (warp w owns cols [32w,32w+32)) ----
    const int n0w = w * 32;
    float acc1[32];
#pragma unroll
    for (int nt = 0; nt < 4; ++nt) {
        float bb0 = sm[FMB1 + n0w + nt * 8 + 2 * lm];
        float bb1 = sm[FMB1 + n0w + nt * 8 + 2 * lm + 1];
#pragma unroll
        for (int mt = 0; mt < 2; ++mt) {
            acc1[(mt * 4 + nt) * 4 + 0] = bb0;
            acc1[(mt * 4 + nt) * 4 + 1] = bb1;
            acc1[(mt * 4 + nt) * 4 + 2] = bb0;
            acc1[(mt * 4 + nt) * 4 + 3] = bb1;
        }
    }
    for (int c4 = 0; c4 < 4; ++c4) {
        __syncthreads();   // X ready (c4=0) / prior WT reads done
        {
            const float4* w4 = (const float4*)(mw1 + c4 * 32 * 256);
            for (int idx = tid; idx < 2048; idx += 256) {
                int r = idx >> 6, v = idx & 63;
                float4 x = w4[r * 64 + v];
                uint4 u = make_uint4(f2tf(x.x), f2tf(x.y), f2tf(x.z), f2tf(x.w));
                *(uint4*)(smu + FWT + r * FPW + v * 4) = u;
            }
        }
        __syncthreads();
#pragma unroll
        for (int s = 0; s < 4; ++s) {
            unsigned int a0[2], a1[2], a2[2], a3[2];
#pragma unroll
            for (int mt = 0; mt < 2; ++mt) {
                const unsigned int* ab =
                    smu + FX + (mt * 16 + l4) * FPX + c4 * 32 + s * 8 + lm;
                a0[mt] = ab[0];
                a1[mt] = ab[8 * FPX];
                a2[mt] = ab[4];
                a3[mt] = ab[8 * FPX + 4];
            }
#pragma unroll
            for (int nt = 0; nt < 4; ++nt) {
                unsigned int b0v = smu[FWT + (s * 8 + lm) * FPW + n0w + nt * 8 + l4];
                unsigned int b1v = smu[FWT + (s * 8 + lm + 4) * FPW + n0w + nt * 8 + l4];
#pragma unroll
                for (int mt = 0; mt < 2; ++mt) {
                    int base = (mt * 4 + nt) * 4;
                    mma_tf32(acc1[base + 0], acc1[base + 1], acc1[base + 2], acc1[base + 3],
                             a0[mt], a1[mt], a2[mt], a3[mt], b0v, b1v);
                }
            }
        }
    }
    // ---- G1 = relu(acc1) as tf32 bits ----
#pragma unroll
    for (int mt = 0; mt < 2; ++mt)
#pragma unroll
        for (int nt = 0; nt < 4; ++nt) {
            int base = (mt * 4 + nt) * 4;
            int col = n0w + nt * 8 + 2 * lm;
            uint2 lo = make_uint2(f2tf(fmaxf(acc1[base + 0], 0.f)),
                                  f2tf(fmaxf(acc1[base + 1], 0.f)));
            uint2 hi = make_uint2(f2tf(fmaxf(acc1[base + 2], 0.f)),
                                  f2tf(fmaxf(acc1[base + 3], 0.f)));
            *(uint2*)(smu + FG1 + (mt * 16 + l4) * FPW + col)     = lo;
            *(uint2*)(smu + FG1 + (mt * 16 + l4 + 8) * FPW + col) = hi;
        }

    // ---- stage 2: acc2 = G1 @ mw2 + mb2 (warp w owns cols [16w,16w+16)) ----
    const int n0w2 = w * 16;
    float acc2[16];
#pragma unroll
    for (int nt = 0; nt < 2; ++nt) {
        float bb0 = sm[FMB2 + n0w2 + nt * 8 + 2 * lm];
        float bb1 = sm[FMB2 + n0w2 + nt * 8 + 2 * lm + 1];
#pragma unroll
        for (int mt = 0; mt < 2; ++mt) {
            acc2[(mt * 2 + nt) * 4 + 0] = bb0;
            acc2[(mt * 2 + nt) * 4 + 1] = bb1;
            acc2[(mt * 2 + nt) * 4 + 2] = bb0;
            acc2[(mt * 2 + nt) * 4 + 3] = bb1;
        }
    }
    for (int c8 = 0; c8 < 8; ++c8) {
        __syncthreads();   // G1 writes done (c8=0) / prior WT reads done
        {
            const float4* w4 = (const float4*)(mw2 + c8 * 32 * 128);
            for (int idx = tid; idx < 1024; idx += 256) {
                int r = idx >> 5, v = idx & 31;
                float4 x = w4[r * 32 + v];
                uint4 u = make_uint4(f2tf(x.x), f2tf(x.y), f2tf(x.z), f2tf(x.w));
                *(uint4*)(smu + FWT + r * FPX + v * 4) = u;
            }
        }
        __syncthreads();
#pragma unroll
        for (int s = 0; s < 4; ++s) {
            unsigned int a0[2], a1[2], a2[2], a3[2];
#pragma unroll
            for (int mt = 0; mt < 2; ++mt) {
                const unsigned int* ab =
                    smu + FG1 + (mt * 16 + l4) * FPW + c8 * 32 + s * 8 + lm;
                a0[mt] = ab[0];
                a1[mt] = ab[8 * FPW];
                a2[mt] = ab[4];
                a3[mt] = ab[8 * FPW + 4];
            }
#pragma unroll
            for (int nt = 0; nt < 2; ++nt) {
                unsigned int b0v = smu[FWT + (s * 8 + lm) * FPX + n0w2 + nt * 8 + l4];
                unsigned int b1v = smu[FWT + (s * 8 + lm + 4) * FPX + n0w2 + nt * 8 + l4];
#pragma unroll
                for (int mt = 0; mt < 2; ++mt) {
                    int base = (mt * 2 + nt) * 4;
                    mma_tf32(acc2[base + 0], acc2[base + 1], acc2[base + 2], acc2[base + 3],
                             a0[mt], a1[mt], a2[mt], a3[mt], b0v, b1v);
                }
            }
        }
    }

    // ---- stage 3: out = relu(acc2) @ ow + ob ----
    float pA[2] = {0.f, 0.f}, pB[2] = {0.f, 0.f};
#pragma unroll
    for (int mt = 0; mt < 2; ++mt)
#pragma unroll
        for (int nt = 0; nt < 2; ++nt) {
            int base = (mt * 2 + nt) * 4;
            float w0 = sm[FOW + n0w2 + nt * 8 + 2 * lm];
            float w1 = sm[FOW + n0w2 + nt * 8 + 2 * lm + 1];
            pA[mt] = fmaf(fmaxf(acc2[base + 0], 0.f), w0,
                     fmaf(fmaxf(acc2[base + 1], 0.f), w1, pA[mt]));
            pB[mt] = fmaf(fmaxf(acc2[base + 2], 0.f), w0,
                     fmaf(fmaxf(acc2[base + 3], 0.f), w1, pB[mt]));
        }
#pragma unroll
    for (int mt = 0; mt < 2; ++mt) {
        pA[mt] += __shfl_xor_sync(0xffffffffu, pA[mt], 1);
        pA[mt] += __shfl_xor_sync(0xffffffffu, pA[mt], 2);
        pB[mt] += __shfl_xor_sync(0xffffffffu, pB[mt], 1);
        pB[mt] += __shfl_xor_sync(0xffffffffu, pB[mt], 2);
    }
    if (lm == 0) {
#pragma unroll
        for (int mt = 0; mt < 2; ++mt) {
            sm[FRED + w * 32 + mt * 16 + l4]     = pA[mt];
            sm[FRED + w * 32 + mt * 16 + l4 + 8] = pB[mt];
        }
    }
    __syncthreads();
    if (tid < DR) {
        float p = ob[0];
#pragma unroll
        for (int w8 = 0; w8 < 8; ++w8) p += sm[FRED + w8 * 32 + tid];
        out[b0 + tid] = p;
    }
}

// ============================================================
// launch
// ============================================================
extern "C" void kernel_launch(void* const* d_in, const int* in_sizes, int n_in,
                              void* d_out, int out_size) {
    const int*   target  = (const int*)d_in[0];
    const int*   hist_id = (const int*)d_in[1];
    const int*   mask    = (const int*)d_in[2];     // bool promoted; test != 0
    const float* table   = (const float*)d_in[3];
    const float* aw1     = (const float*)d_in[4];
    const float* ab1     = (const float*)d_in[5];
    const float* aw2     = (const float*)d_in[6];
    const float* ab2     = (const float*)d_in[7];
    const float* aow     = (const float*)d_in[8];
    const float* aob     = (const float*)d_in[9];
    const float* mw1     = (const float*)d_in[10];
    const float* mb1     = (const float*)d_in[11];
    const float* mw2     = (const float*)d_in[12];
    const float* mb2     = (const float*)d_in[13];
    const float* ow      = (const float*)d_in[14];
    const float* ob      = (const float*)d_in[15];
    float* out = (float*)d_out;

    cudaFuncSetAttribute(din_main, cudaFuncAttributeMaxDynamicSharedMemorySize, SMEM_B_BYTES);
    cudaFuncSetAttribute(din_final, cudaFuncAttributeMaxDynamicSharedMemorySize, SMEM_F_BYTES);

    prep_weights<<<8, 512>>>(aw1);
    din_main<<<GRID_MAIN, 512, SMEM_B_BYTES>>>(hist_id, mask, table, target, ab1,
                                               aw2, ab2, aow, aob);
    din_final<<<B_ / DR, 256, SMEM_F_BYTES>>>(target, table, mw1, mb1,
                                              mw2, mb2, ow, ob, out);
}